// round 1
// baseline (speedup 1.0000x reference)
#include <cuda_runtime.h>
#include <math.h>

// ---------------- problem constants ----------------
#define V_NODES 100000
#define F_DIM   512
#define D_DIM   512
#define C_DIM   128
#define N1_CNT  36864
#define S1_CNT  32768
#define B1_CNT  4096
#define S2_CNT  3584
#define B2_CNT  512

// ---------------- scratch (device globals; no allocation allowed) ----------------
__device__ float g_cat1[B1_CNT * 1024];   // [4096, 1024]  = [agg1 | dst1]
__device__ float g_h1  [B1_CNT * D_DIM];  // [4096, 512]
__device__ float g_cat2[B2_CNT * 1024];   // [512, 1024]   = [agg2 | dst2]
__device__ float g_h2  [B2_CNT * D_DIM];  // [512, 512]
__device__ int   g_gidx1[S1_CNT];         // src_nodes[src_idx1[k]]

typedef unsigned long long u64t;

// ---------------- packed f32x2 helpers ----------------
__device__ __forceinline__ u64t pack_dup(float a) {
    u64t r; asm("mov.b64 %0, {%1, %1};" : "=l"(r) : "f"(a)); return r;
}
__device__ __forceinline__ void fma2(u64t& d, u64t a, u64t b) {
    asm("fma.rn.f32x2 %0, %1, %2, %0;" : "+l"(d) : "l"(a), "l"(b));
}
__device__ __forceinline__ float2 unpack2(u64t v) {
    float lo, hi; asm("mov.b64 {%0, %1}, %2;" : "=f"(lo), "=f"(hi) : "l"(v));
    return make_float2(lo, hi);
}

// ---------------- index composition ----------------
__global__ void build_gidx_kernel(const int* __restrict__ src_nodes,
                                  const int* __restrict__ src_idx1,
                                  int* __restrict__ out, int n) {
    int k = blockIdx.x * blockDim.x + threadIdx.x;
    if (k < n) out[k] = src_nodes[src_idx1[k]];
}

// gather one 512-float row into the second half of a 1024-wide cat row
// map != nullptr: row = map[idx[b]] (layer 1, composed); else row = idx[b]
__global__ void gather_cat_kernel(const float* __restrict__ src,
                                  const int* __restrict__ idx,
                                  const int* __restrict__ map,
                                  float* __restrict__ cat) {
    int b = blockIdx.x;
    int r = idx[b];
    if (map) r = map[r];
    const float4* s = reinterpret_cast<const float4*>(src + (size_t)r * 512);
    float4* d = reinterpret_cast<float4*>(cat + (size_t)b * 1024 + 512);
    d[threadIdx.x] = s[threadIdx.x];   // 128 threads x float4 = 512 floats
}

// ---------------- tiled SGEMM, f32x2 inner product ----------------
// C[M,N] = A[M,K] @ B[K,N]; optional row-gather on B; optional ReLU on output.
template<int BM, int BN, int BK, int TM, int TN, bool GATHER_B, bool RELU>
__global__ __launch_bounds__((BM / TM) * (BN / TN))
void sgemm_kernel(int M, int N, int K,
                  const float* __restrict__ A, int lda,
                  const float* __restrict__ B, int ldb,
                  const int* __restrict__ bidx,
                  float* __restrict__ C, int ldc) {
    constexpr int THREADS = (BM / TM) * (BN / TN);
    __shared__ __align__(16) float As[BK][BM];   // transposed A tile
    __shared__ __align__(16) float Bs[BK][BN];

    const int tid = threadIdx.x;
    const int block_m = blockIdx.y * BM;
    const int block_n = blockIdx.x * BN;

    const int tn = (tid % (BN / TN)) * TN;
    const int tm = (tid / (BN / TN)) * TM;

    u64t acc2[TM][TN / 2];
#pragma unroll
    for (int i = 0; i < TM; ++i)
#pragma unroll
        for (int j = 0; j < TN / 2; ++j) acc2[i][j] = 0ull;

    constexpr int LA = (BM * BK) / (4 * THREADS);   // float4 per thread for A
    constexpr int LB = (BK * BN) / (4 * THREADS);   // float4 per thread for B
    constexpr int A_F4_PER_ROW = BK / 4;
    constexpr int B_F4_PER_ROW = BN / 4;

    for (int k0 = 0; k0 < K; k0 += BK) {
        // ---- load A tile (BM x BK), store transposed ----
#pragma unroll
        for (int i = 0; i < LA; ++i) {
            int idx = tid + i * THREADS;
            int row = idx / A_F4_PER_ROW;
            int c4  = idx % A_F4_PER_ROW;
            float4 v = *reinterpret_cast<const float4*>(
                A + (size_t)(block_m + row) * lda + k0 + c4 * 4);
            As[c4 * 4 + 0][row] = v.x;
            As[c4 * 4 + 1][row] = v.y;
            As[c4 * 4 + 2][row] = v.z;
            As[c4 * 4 + 3][row] = v.w;
        }
        // ---- load B tile (BK x BN), optional row gather ----
#pragma unroll
        for (int i = 0; i < LB; ++i) {
            int idx = tid + i * THREADS;
            int row = idx / B_F4_PER_ROW;
            int c4  = idx % B_F4_PER_ROW;
            const float* brow;
            if (GATHER_B)
                brow = B + (size_t)bidx[k0 + row] * ldb;
            else
                brow = B + (size_t)(k0 + row) * ldb;
            float4 v = *reinterpret_cast<const float4*>(brow + block_n + c4 * 4);
            *reinterpret_cast<float4*>(&Bs[row][c4 * 4]) = v;
        }
        __syncthreads();

        // ---- compute: packed f32x2 FMAs (fma pipe), packing movs on alu pipe ----
#pragma unroll
        for (int kk = 0; kk < BK; ++kk) {
            u64t b2[TN / 2];
            const u64t* bs2 = reinterpret_cast<const u64t*>(&Bs[kk][tn]);
#pragma unroll
            for (int j = 0; j < TN / 2; ++j) b2[j] = bs2[j];
#pragma unroll
            for (int i = 0; i < TM; ++i) {
                u64t a2 = pack_dup(As[kk][tm + i]);
#pragma unroll
                for (int j = 0; j < TN / 2; ++j) fma2(acc2[i][j], a2, b2[j]);
            }
        }
        __syncthreads();
    }

    // ---- epilogue ----
#pragma unroll
    for (int i = 0; i < TM; ++i) {
        float* crow = C + (size_t)(block_m + tm + i) * ldc + block_n + tn;
#pragma unroll
        for (int j = 0; j < TN / 2; j += 2) {
            float2 v0 = unpack2(acc2[i][j]);
            float2 v1 = unpack2(acc2[i][j + 1]);
            float4 o;
            if (RELU) {
                o.x = fmaxf(v0.x, 0.f); o.y = fmaxf(v0.y, 0.f);
                o.z = fmaxf(v1.x, 0.f); o.w = fmaxf(v1.y, 0.f);
            } else {
                o.x = v0.x; o.y = v0.y; o.z = v1.x; o.w = v1.y;
            }
            *reinterpret_cast<float4*>(crow + j * 2) = o;
        }
    }
}

// ---------------- classifier + softmax (one CTA per output row) ----------------
__global__ void cls_softmax_kernel(const float* __restrict__ h2,
                                   const float* __restrict__ wc,
                                   float* __restrict__ out) {
    __shared__ float sh[D_DIM];
    __shared__ float red[C_DIM];
    const int b = blockIdx.x;
    const int c = threadIdx.x;

    for (int i = c; i < D_DIM; i += C_DIM) sh[i] = h2[(size_t)b * D_DIM + i];
    __syncthreads();

    float acc = 0.f;
#pragma unroll 8
    for (int k = 0; k < D_DIM; ++k)
        acc = fmaf(sh[k], wc[(size_t)k * C_DIM + c], acc);

    // max-reduce over 128 threads
    red[c] = acc;
    __syncthreads();
    for (int s = C_DIM / 2; s > 0; s >>= 1) {
        if (c < s) red[c] = fmaxf(red[c], red[c + s]);
        __syncthreads();
    }
    float mx = red[0];
    __syncthreads();

    float e = expf(acc - mx);
    red[c] = e;
    __syncthreads();
    for (int s = C_DIM / 2; s > 0; s >>= 1) {
        if (c < s) red[c] += red[c + s];
        __syncthreads();
    }
    out[(size_t)b * C_DIM + c] = e / red[0];
}

// ---------------- launch ----------------
extern "C" void kernel_launch(void* const* d_in, const int* in_sizes, int n_in,
                              void* d_out, int out_size) {
    const float* features = (const float*)d_in[0];
    const int*   src_nodes = (const int*)d_in[1];
    const int*   dst_idx1  = (const int*)d_in[2];
    const int*   src_idx1  = (const int*)d_in[3];
    const float* dif_mat1  = (const float*)d_in[4];
    const int*   dst_idx2  = (const int*)d_in[5];
    const int*   src_idx2  = (const int*)d_in[6];
    const float* dif_mat2  = (const float*)d_in[7];
    const float* w1        = (const float*)d_in[8];
    const float* w2        = (const float*)d_in[9];
    const float* w_cls     = (const float*)d_in[10];
    float* out = (float*)d_out;

    float *cat1, *h1, *cat2, *h2;
    int* gidx1;
    cudaGetSymbolAddress((void**)&cat1, g_cat1);
    cudaGetSymbolAddress((void**)&h1,   g_h1);
    cudaGetSymbolAddress((void**)&cat2, g_cat2);
    cudaGetSymbolAddress((void**)&h2,   g_h2);
    cudaGetSymbolAddress((void**)&gidx1, g_gidx1);

    // 0) composed gather index for layer-1 source rows
    build_gidx_kernel<<<(S1_CNT + 255) / 256, 256>>>(src_nodes, src_idx1, gidx1, S1_CNT);

    // 1) dst-feature gather into cat1[:, 512:1024]
    gather_cat_kernel<<<B1_CNT, 128>>>(features, dst_idx1, src_nodes, cat1);

    // 2) agg1 = dif_mat1 @ features[gidx1]  -> cat1[:, 0:512]
    sgemm_kernel<128, 128, 16, 8, 8, true, false>
        <<<dim3(F_DIM / 128, B1_CNT / 128), 256>>>(
            B1_CNT, F_DIM, S1_CNT,
            dif_mat1, S1_CNT,
            features, F_DIM, gidx1,
            cat1, 1024);

    // 3) h1 = relu(cat1 @ w1)
    sgemm_kernel<128, 128, 16, 8, 8, false, true>
        <<<dim3(D_DIM / 128, B1_CNT / 128), 256>>>(
            B1_CNT, D_DIM, 2 * F_DIM,
            cat1, 1024,
            w1, D_DIM, nullptr,
            h1, D_DIM);

    // 4) dst gather into cat2[:, 512:1024]
    gather_cat_kernel<<<B2_CNT, 128>>>(h1, dst_idx2, nullptr, cat2);

    // 5) agg2 = dif_mat2 @ h1[src_idx2] -> cat2[:, 0:512]
    sgemm_kernel<64, 64, 16, 4, 4, true, false>
        <<<dim3(D_DIM / 64, B2_CNT / 64), 256>>>(
            B2_CNT, D_DIM, S2_CNT,
            dif_mat2, S2_CNT,
            h1, D_DIM, src_idx2,
            cat2, 1024);

    // 6) h2 = relu(cat2 @ w2)
    sgemm_kernel<64, 64, 16, 4, 4, false, true>
        <<<dim3(D_DIM / 64, B2_CNT / 64), 256>>>(
            B2_CNT, D_DIM, 2 * D_DIM,
            cat2, 1024,
            w2, D_DIM, nullptr,
            h2, D_DIM);

    // 7) out = softmax(h2 @ w_cls)
    cls_softmax_kernel<<<B2_CNT, C_DIM>>>(h2, w_cls, out);
}

// round 3
// speedup vs baseline: 2.6812x; 2.6812x over previous
#include <cuda_runtime.h>
#include <cuda_bf16.h>
#include <cstdint>
#include <math.h>

// ---------------- problem constants ----------------
#define V_NODES 100000
#define F_DIM   512
#define D_DIM   512
#define C_DIM   128
#define N1_CNT  36864
#define S1_CNT  32768
#define B1_CNT  4096
#define S2_CNT  3584
#define B2_CNT  512

// ---------------- scratch (device globals; no allocation allowed) ----------------
__device__ float g_cat1[B1_CNT * 1024];   // [4096, 1024]  = [agg1 | dst1]
__device__ float g_h1  [B1_CNT * D_DIM];  // [4096, 512]
__device__ float g_cat2[B2_CNT * 1024];   // [512, 1024]
__device__ float g_h2  [B2_CNT * D_DIM];  // [512, 512]
__device__ int   g_gidx1[S1_CNT];         // src_nodes[src_idx1[k]]
__device__ __nv_bfloat16 g_xhi[(size_t)S1_CNT * F_DIM];  // X hi  [32768, 512] row-major
__device__ __nv_bfloat16 g_xlo[(size_t)S1_CNT * F_DIM];  // X lo

typedef unsigned long long u64t;

// ================= baseline-PTX helpers (work on compute_103) =================
__device__ __forceinline__ uint32_t smem_u32(const void* p) {
    uint32_t a;
    asm("{ .reg .u64 t; cvta.to.shared.u64 t, %1; cvt.u32.u64 %0, t; }" : "=r"(a) : "l"(p));
    return a;
}
#define CP_ASYNC16(sm, gm) asm volatile("cp.async.cg.shared.global [%0], [%1], 16;" :: "r"(sm), "l"(gm) : "memory")
#define CP_COMMIT()        asm volatile("cp.async.commit_group;" ::: "memory")
#define CP_WAIT0()         asm volatile("cp.async.wait_group 0;" ::: "memory")

__device__ __forceinline__ void ldsm_x4(uint32_t* r, uint32_t addr) {
    asm volatile("ldmatrix.sync.aligned.m8n8.x4.shared.b16 {%0,%1,%2,%3}, [%4];"
        : "=r"(r[0]), "=r"(r[1]), "=r"(r[2]), "=r"(r[3]) : "r"(addr));
}
__device__ __forceinline__ void ldsm_x4_t(uint32_t* r, uint32_t addr) {
    asm volatile("ldmatrix.sync.aligned.m8n8.x4.trans.shared.b16 {%0,%1,%2,%3}, [%4];"
        : "=r"(r[0]), "=r"(r[1]), "=r"(r[2]), "=r"(r[3]) : "r"(addr));
}
__device__ __forceinline__ void mma16816(float* d, const uint32_t* a, const uint32_t* b) {
    asm volatile("mma.sync.aligned.m16n8k16.row.col.f32.bf16.bf16.f32 "
        "{%0,%1,%2,%3}, {%4,%5,%6,%7}, {%8,%9}, {%0,%1,%2,%3};"
        : "+f"(d[0]), "+f"(d[1]), "+f"(d[2]), "+f"(d[3])
        : "r"(a[0]), "r"(a[1]), "r"(a[2]), "r"(a[3]), "r"(b[0]), "r"(b[1]));
}
__device__ __forceinline__ uint32_t pack_bf2(__nv_bfloat16 a, __nv_bfloat16 b) {
    __nv_bfloat162 t = __halves2bfloat162(a, b);
    return *reinterpret_cast<uint32_t*>(&t);
}
__device__ __forceinline__ void split_bf(float f, __nv_bfloat16& hi, __nv_bfloat16& lo) {
    hi = __float2bfloat16(f);
    lo = __float2bfloat16(f - __bfloat162float(hi));
}

// ---------------- packed f32x2 helpers (small-GEMM path) ----------------
__device__ __forceinline__ u64t pack_dup(float a) {
    u64t r; asm("mov.b64 %0, {%1, %1};" : "=l"(r) : "f"(a)); return r;
}
__device__ __forceinline__ void fma2(u64t& d, u64t a, u64t b) {
    asm("fma.rn.f32x2 %0, %1, %2, %0;" : "+l"(d) : "l"(a), "l"(b));
}
__device__ __forceinline__ float2 unpack2(u64t v) {
    float lo, hi; asm("mov.b64 {%0, %1}, %2;" : "=f"(lo), "=f"(hi) : "l"(v));
    return make_float2(lo, hi);
}

// ================= small kernels =================
__global__ void build_gidx_kernel(const int* __restrict__ src_nodes,
                                  const int* __restrict__ src_idx1,
                                  int* __restrict__ out, int n) {
    int k = blockIdx.x * blockDim.x + threadIdx.x;
    if (k < n) out[k] = src_nodes[src_idx1[k]];
}

__global__ void gather_cat_kernel(const float* __restrict__ src,
                                  const int* __restrict__ idx,
                                  const int* __restrict__ map,
                                  float* __restrict__ cat) {
    int b = blockIdx.x;
    int r = idx[b];
    if (map) r = map[r];
    const float4* s = reinterpret_cast<const float4*>(src + (size_t)r * 512);
    float4* d = reinterpret_cast<float4*>(cat + (size_t)b * 1024 + 512);
    d[threadIdx.x] = s[threadIdx.x];
}

// gather + bf16 hi/lo split, row-major: X[k][:] = features[gidx[k]][:]
__global__ void prep_x_kernel(const float* __restrict__ features,
                              const int* __restrict__ gidx,
                              __nv_bfloat16* __restrict__ xhi,
                              __nv_bfloat16* __restrict__ xlo) {
    const int k = blockIdx.x;
    const int r = gidx[k];
    float4 v = reinterpret_cast<const float4*>(features + (size_t)r * F_DIM)[threadIdx.x];
    __nv_bfloat16 h0, h1, h2, h3, l0, l1, l2, l3;
    split_bf(v.x, h0, l0); split_bf(v.y, h1, l1);
    split_bf(v.z, h2, l2); split_bf(v.w, h3, l3);
    uint2 hv = make_uint2(pack_bf2(h0, h1), pack_bf2(h2, h3));
    uint2 lv = make_uint2(pack_bf2(l0, l1), pack_bf2(l2, l3));
    reinterpret_cast<uint2*>(xhi + (size_t)k * F_DIM)[threadIdx.x] = hv;
    reinterpret_cast<uint2*>(xlo + (size_t)k * F_DIM)[threadIdx.x] = lv;
}

// ================= GEMM1: HMMA bf16 3-term (hi/lo) =================
// C[4096, 512] (cat1 cols 0:512, ldc=1024) = dif_mat1[4096,32768] @ X[32768,512]
#define BM 128
#define BN 128
#define BKC 64
#define NCH (S1_CNT / BKC)          // 512
#define A_STRIDE 144                // bytes per A smem row (64 bf16 + 8 pad)
#define A_BYTES (BM * A_STRIDE)     // 18432 per dtype
#define B_STRIDE 256                // bytes per B smem row (128 bf16)
#define B_BYTES (BKC * B_STRIDE)    // 16384 per dtype
#define STAGE_BYTES (2 * A_BYTES + 2 * B_BYTES)   // 69632
#define G1_SMEM (2 * STAGE_BYTES)                  // 139264

__global__ __launch_bounds__(256, 1)
void gemm1_mma_kernel(const float* __restrict__ A,
                      const __nv_bfloat16* __restrict__ Xhi,
                      const __nv_bfloat16* __restrict__ Xlo,
                      float* __restrict__ C, int ldc) {
    extern __shared__ __align__(128) char smem[];
    const uint32_t sb = smem_u32(smem);
    const int tid = threadIdx.x;
    const int wid = tid >> 5;
    const int lane = tid & 31;
    const int bm = blockIdx.y * BM;
    const int bn = blockIdx.x * BN;
    const int wm = (wid & 3) * 32;
    const int wn = (wid >> 2) * 64;

    float acc[2][8][4];
#pragma unroll
    for (int m = 0; m < 2; ++m)
#pragma unroll
        for (int n = 0; n < 8; ++n)
#pragma unroll
            for (int j = 0; j < 4; ++j) acc[m][n][j] = 0.f;

    const int arow = tid >> 1;            // 0..127
    const int acol = (tid & 1) * 32;      // fp32 col base within chunk

    // ---- helpers as macros over locals ----
#define LOAD_B(ch, stg) do {                                                  \
    size_t k0 = (size_t)(ch) * BKC;                                           \
    uint32_t bb = sb + (stg) * STAGE_BYTES + 2 * A_BYTES;                     \
    _Pragma("unroll")                                                         \
    for (int i = 0; i < 4; ++i) {                                             \
        int lin = tid + i * 256;                                              \
        int row = lin >> 4;                                                   \
        int chk = lin & 15;                                                   \
        uint32_t dst = bb + row * B_STRIDE + ((chk ^ (row & 7)) << 4);        \
        const __nv_bfloat16* sh = Xhi + (k0 + row) * F_DIM + bn + chk * 8;    \
        const __nv_bfloat16* sl = Xlo + (k0 + row) * F_DIM + bn + chk * 8;    \
        CP_ASYNC16(dst, sh);                                                  \
        CP_ASYNC16(dst + B_BYTES, sl);                                        \
    }                                                                         \
} while (0)

#define LOAD_A_REGS(ch, regs) do {                                            \
    const float4* src = reinterpret_cast<const float4*>(                      \
        A + (size_t)(bm + arow) * S1_CNT + (size_t)(ch) * BKC + acol);        \
    _Pragma("unroll")                                                         \
    for (int j = 0; j < 8; ++j) (regs)[j] = src[j];                           \
} while (0)

#define STORE_A(stg, regs) do {                                               \
    char* ab = smem + (stg) * STAGE_BYTES + arow * A_STRIDE + acol * 2;       \
    _Pragma("unroll")                                                         \
    for (int j = 0; j < 2; ++j) {                                             \
        float f[16] = { (regs)[4*j+0].x, (regs)[4*j+0].y, (regs)[4*j+0].z, (regs)[4*j+0].w, \
                        (regs)[4*j+1].x, (regs)[4*j+1].y, (regs)[4*j+1].z, (regs)[4*j+1].w, \
                        (regs)[4*j+2].x, (regs)[4*j+2].y, (regs)[4*j+2].z, (regs)[4*j+2].w, \
                        (regs)[4*j+3].x, (regs)[4*j+3].y, (regs)[4*j+3].z, (regs)[4*j+3].w };\
        __nv_bfloat16 h[16], l[16];                                           \
        _Pragma("unroll")                                                     \
        for (int q = 0; q < 16; ++q) split_bf(f[q], h[q], l[q]);              \
        uint4 hv0 = make_uint4(pack_bf2(h[0],h[1]),  pack_bf2(h[2],h[3]),     \
                               pack_bf2(h[4],h[5]),  pack_bf2(h[6],h[7]));    \
        uint4 hv1 = make_uint4(pack_bf2(h[8],h[9]),  pack_bf2(h[10],h[11]),   \
                               pack_bf2(h[12],h[13]),pack_bf2(h[14],h[15]));  \
        uint4 lv0 = make_uint4(pack_bf2(l[0],l[1]),  pack_bf2(l[2],l[3]),     \
                               pack_bf2(l[4],l[5]),  pack_bf2(l[6],l[7]));    \
        uint4 lv1 = make_uint4(pack_bf2(l[8],l[9]),  pack_bf2(l[10],l[11]),   \
                               pack_bf2(l[12],l[13]),pack_bf2(l[14],l[15]));  \
        *reinterpret_cast<uint4*>(ab + j * 32)            = hv0;              \
        *reinterpret_cast<uint4*>(ab + j * 32 + 16)       = hv1;              \
        *reinterpret_cast<uint4*>(ab + A_BYTES + j * 32)      = lv0;          \
        *reinterpret_cast<uint4*>(ab + A_BYTES + j * 32 + 16) = lv1;          \
    }                                                                         \
} while (0)

    // ---- prologue: stage 0 ----
    float4 areg[8];
    LOAD_B(0, 0); CP_COMMIT();
    LOAD_A_REGS(0, areg);
    STORE_A(0, areg);
    CP_WAIT0();
    __syncthreads();

    for (int ch = 0; ch < NCH; ++ch) {
        const int stg = ch & 1;
        const bool more = (ch + 1 < NCH);
        if (more) {
            LOAD_B(ch + 1, stg ^ 1); CP_COMMIT();
            LOAD_A_REGS(ch + 1, areg);
        }

        // ---- compute on stage stg ----
        const uint32_t abase = sb + stg * STAGE_BYTES;
        const uint32_t bbase = abase + 2 * A_BYTES;
#pragma unroll
        for (int kk = 0; kk < 4; ++kk) {
            uint32_t ah[2][4], al[2][4];
#pragma unroll
            for (int m = 0; m < 2; ++m) {
                uint32_t r = wm + m * 16 + (lane & 15);
                uint32_t col = kk * 32 + (lane >> 4) * 16;
                uint32_t ad = abase + r * A_STRIDE + col;
                ldsm_x4(ah[m], ad);
                ldsm_x4(al[m], ad + A_BYTES);
            }
            uint32_t bh[4][4], bl[4][4];
#pragma unroll
            for (int j = 0; j < 4; ++j) {
                uint32_t krow = kk * 16 + (lane & 15);
                uint32_t chk = (uint32_t)(wn >> 3) + j * 2 + (lane >> 4);
                uint32_t bd = bbase + krow * B_STRIDE + ((chk ^ (krow & 7)) << 4);
                ldsm_x4_t(bh[j], bd);
                ldsm_x4_t(bl[j], bd + B_BYTES);
            }
#pragma unroll
            for (int m = 0; m < 2; ++m)
#pragma unroll
                for (int j = 0; j < 4; ++j)
#pragma unroll
                    for (int h = 0; h < 2; ++h) {
                        const int n8 = j * 2 + h;
                        mma16816(acc[m][n8], ah[m], &bh[j][2 * h]);
                        mma16816(acc[m][n8], ah[m], &bl[j][2 * h]);
                        mma16816(acc[m][n8], al[m], &bh[j][2 * h]);
                    }
        }

        if (more) {
            STORE_A(stg ^ 1, areg);
            CP_WAIT0();
        }
        __syncthreads();
    }

    // ---- epilogue ----
#pragma unroll
    for (int m = 0; m < 2; ++m) {
        const int row = bm + wm + m * 16 + (lane >> 2);
#pragma unroll
        for (int n8 = 0; n8 < 8; ++n8) {
            const int col = bn + wn + n8 * 8 + (lane & 3) * 2;
            *reinterpret_cast<float2*>(C + (size_t)row * ldc + col) =
                make_float2(acc[m][n8][0], acc[m][n8][1]);
            *reinterpret_cast<float2*>(C + (size_t)(row + 8) * ldc + col) =
                make_float2(acc[m][n8][2], acc[m][n8][3]);
        }
    }
#undef LOAD_B
#undef LOAD_A_REGS
#undef STORE_A
}

// ================= f32x2 SGEMM (small GEMMs) =================
template<int BMt, int BNt, int BKt, int TM, int TN, bool GATHER_B, bool RELU>
__global__ __launch_bounds__((BMt / TM) * (BNt / TN))
void sgemm_kernel(int M, int N, int K,
                  const float* __restrict__ Am, int lda,
                  const float* __restrict__ Bm, int ldb,
                  const int* __restrict__ bidx,
                  float* __restrict__ Cm, int ldc) {
    constexpr int THREADS = (BMt / TM) * (BNt / TN);
    __shared__ __align__(16) float As[BKt][BMt];
    __shared__ __align__(16) float Bs[BKt][BNt];

    const int tid = threadIdx.x;
    const int block_m = blockIdx.y * BMt;
    const int block_n = blockIdx.x * BNt;
    const int tn = (tid % (BNt / TN)) * TN;
    const int tm = (tid / (BNt / TN)) * TM;

    u64t acc2[TM][TN / 2];
#pragma unroll
    for (int i = 0; i < TM; ++i)
#pragma unroll
        for (int j = 0; j < TN / 2; ++j) acc2[i][j] = 0ull;

    constexpr int LA = (BMt * BKt) / (4 * THREADS);
    constexpr int LB = (BKt * BNt) / (4 * THREADS);
    constexpr int A_F4_PER_ROW = BKt / 4;
    constexpr int B_F4_PER_ROW = BNt / 4;

    for (int k0 = 0; k0 < K; k0 += BKt) {
#pragma unroll
        for (int i = 0; i < LA; ++i) {
            int idx = tid + i * THREADS;
            int row = idx / A_F4_PER_ROW;
            int c4  = idx % A_F4_PER_ROW;
            float4 v = *reinterpret_cast<const float4*>(
                Am + (size_t)(block_m + row) * lda + k0 + c4 * 4);
            As[c4 * 4 + 0][row] = v.x;
            As[c4 * 4 + 1][row] = v.y;
            As[c4 * 4 + 2][row] = v.z;
            As[c4 * 4 + 3][row] = v.w;
        }
#pragma unroll
        for (int i = 0; i < LB; ++i) {
            int idx = tid + i * THREADS;
            int row = idx / B_F4_PER_ROW;
            int c4  = idx % B_F4_PER_ROW;
            const float* brow;
            if (GATHER_B) brow = Bm + (size_t)bidx[k0 + row] * ldb;
            else          brow = Bm + (size_t)(k0 + row) * ldb;
            float4 v = *reinterpret_cast<const float4*>(brow + block_n + c4 * 4);
            *reinterpret_cast<float4*>(&Bs[row][c4 * 4]) = v;
        }
        __syncthreads();
#pragma unroll
        for (int kk = 0; kk < BKt; ++kk) {
            u64t b2[TN / 2];
            const u64t* bs2 = reinterpret_cast<const u64t*>(&Bs[kk][tn]);
#pragma unroll
            for (int j = 0; j < TN / 2; ++j) b2[j] = bs2[j];
#pragma unroll
            for (int i = 0; i < TM; ++i) {
                u64t a2 = pack_dup(As[kk][tm + i]);
#pragma unroll
                for (int j = 0; j < TN / 2; ++j) fma2(acc2[i][j], a2, b2[j]);
            }
        }
        __syncthreads();
    }
#pragma unroll
    for (int i = 0; i < TM; ++i) {
        float* crow = Cm + (size_t)(block_m + tm + i) * ldc + block_n + tn;
#pragma unroll
        for (int j = 0; j < TN / 2; j += 2) {
            float2 v0 = unpack2(acc2[i][j]);
            float2 v1 = unpack2(acc2[i][j + 1]);
            float4 o;
            if (RELU) {
                o.x = fmaxf(v0.x, 0.f); o.y = fmaxf(v0.y, 0.f);
                o.z = fmaxf(v1.x, 0.f); o.w = fmaxf(v1.y, 0.f);
            } else {
                o.x = v0.x; o.y = v0.y; o.z = v1.x; o.w = v1.y;
            }
            *reinterpret_cast<float4*>(crow + j * 2) = o;
        }
    }
}

// ================= classifier + softmax =================
__global__ void cls_softmax_kernel(const float* __restrict__ h2,
                                   const float* __restrict__ wc,
                                   float* __restrict__ out) {
    __shared__ float sh[D_DIM];
    __shared__ float red[C_DIM];
    const int b = blockIdx.x;
    const int c = threadIdx.x;
    for (int i = c; i < D_DIM; i += C_DIM) sh[i] = h2[(size_t)b * D_DIM + i];
    __syncthreads();
    float acc = 0.f;
#pragma unroll 8
    for (int k = 0; k < D_DIM; ++k)
        acc = fmaf(sh[k], wc[(size_t)k * C_DIM + c], acc);
    red[c] = acc;
    __syncthreads();
    for (int s = C_DIM / 2; s > 0; s >>= 1) {
        if (c < s) red[c] = fmaxf(red[c], red[c + s]);
        __syncthreads();
    }
    float mx = red[0];
    __syncthreads();
    float e = expf(acc - mx);
    red[c] = e;
    __syncthreads();
    for (int s = C_DIM / 2; s > 0; s >>= 1) {
        if (c < s) red[c] += red[c + s];
        __syncthreads();
    }
    out[(size_t)b * C_DIM + c] = e / red[0];
}

// ================= launch =================
extern "C" void kernel_launch(void* const* d_in, const int* in_sizes, int n_in,
                              void* d_out, int out_size) {
    const float* features  = (const float*)d_in[0];
    const int*   src_nodes = (const int*)d_in[1];
    const int*   dst_idx1  = (const int*)d_in[2];
    const int*   src_idx1  = (const int*)d_in[3];
    const float* dif_mat1  = (const float*)d_in[4];
    const int*   dst_idx2  = (const int*)d_in[5];
    const int*   src_idx2  = (const int*)d_in[6];
    const float* dif_mat2  = (const float*)d_in[7];
    const float* w1        = (const float*)d_in[8];
    const float* w2        = (const float*)d_in[9];
    const float* w_cls     = (const float*)d_in[10];
    float* out = (float*)d_out;

    float *cat1, *h1, *cat2, *h2;
    int* gidx1;
    __nv_bfloat16 *xhi, *xlo;
    cudaGetSymbolAddress((void**)&cat1,  g_cat1);
    cudaGetSymbolAddress((void**)&h1,    g_h1);
    cudaGetSymbolAddress((void**)&cat2,  g_cat2);
    cudaGetSymbolAddress((void**)&h2,    g_h2);
    cudaGetSymbolAddress((void**)&gidx1, g_gidx1);
    cudaGetSymbolAddress((void**)&xhi,   g_xhi);
    cudaGetSymbolAddress((void**)&xlo,   g_xlo);

    cudaFuncSetAttribute(gemm1_mma_kernel,
                         cudaFuncAttributeMaxDynamicSharedMemorySize, G1_SMEM);

    // 0) composed gather index
    build_gidx_kernel<<<(S1_CNT + 255) / 256, 256>>>(src_nodes, src_idx1, gidx1, S1_CNT);

    // 1) dst-feature gather into cat1[:, 512:1024]
    gather_cat_kernel<<<B1_CNT, 128>>>(features, dst_idx1, src_nodes, cat1);

    // 2) prep: X hi/lo bf16 split [32768, 512] row-major
    prep_x_kernel<<<S1_CNT, 128>>>(features, gidx1, xhi, xlo);

    // 3) agg1 = dif_mat1 @ X -> cat1[:, 0:512]  (HMMA bf16 3-term)
    gemm1_mma_kernel<<<dim3(F_DIM / BN, B1_CNT / BM), 256, G1_SMEM>>>(
        dif_mat1, xhi, xlo, cat1, 1024);

    // 4) h1 = relu(cat1 @ w1)
    sgemm_kernel<128, 128, 16, 8, 8, false, true>
        <<<dim3(D_DIM / 128, B1_CNT / 128), 256>>>(
            B1_CNT, D_DIM, 2 * F_DIM, cat1, 1024, w1, D_DIM, nullptr, h1, D_DIM);

    // 5) dst gather into cat2[:, 512:1024]
    gather_cat_kernel<<<B2_CNT, 128>>>(h1, dst_idx2, nullptr, cat2);

    // 6) agg2 = dif_mat2 @ h1[src_idx2] -> cat2[:, 0:512]
    sgemm_kernel<64, 64, 16, 4, 4, true, false>
        <<<dim3(D_DIM / 64, B2_CNT / 64), 256>>>(
            B2_CNT, D_DIM, S2_CNT, dif_mat2, S2_CNT, h1, D_DIM, src_idx2, cat2, 1024);

    // 7) h2 = relu(cat2 @ w2)
    sgemm_kernel<64, 64, 16, 4, 4, false, true>
        <<<dim3(D_DIM / 64, B2_CNT / 64), 256>>>(
            B2_CNT, D_DIM, 2 * D_DIM, cat2, 1024, w2, D_DIM, nullptr, h2, D_DIM);

    // 8) out = softmax(h2 @ w_cls)
    cls_softmax_kernel<<<B2_CNT, C_DIM>>>(h2, w_cls, out);
}

// round 4
// speedup vs baseline: 3.2943x; 1.2287x over previous
#include <cuda_runtime.h>
#include <cuda_bf16.h>
#include <cstdint>
#include <math.h>

// ---------------- problem constants ----------------
#define V_NODES 100000
#define F_DIM   512
#define D_DIM   512
#define C_DIM   128
#define N1_CNT  36864
#define S1_CNT  32768
#define B1_CNT  4096
#define S2_CNT  3584
#define B2_CNT  512

// ---------------- scratch (device globals; no allocation allowed) ----------------
__device__ float g_cat1[B1_CNT * 1024];
__device__ float g_h1  [B1_CNT * D_DIM];
__device__ float g_cat2[B2_CNT * 1024];
__device__ float g_h2  [B2_CNT * D_DIM];
__device__ int   g_gidx1[S1_CNT];
__device__ __nv_bfloat16 g_ahi[(size_t)B1_CNT * S1_CNT];   // dif_mat1 hi [4096,32768]
__device__ __nv_bfloat16 g_alo[(size_t)B1_CNT * S1_CNT];   // dif_mat1 lo
__device__ __nv_bfloat16 g_xhi[(size_t)S1_CNT * F_DIM];    // X hi [32768,512]
__device__ __nv_bfloat16 g_xlo[(size_t)S1_CNT * F_DIM];
__device__ __nv_bfloat16 g_c1hi[(size_t)B1_CNT * 1024];    // cat1 hi [4096,1024]
__device__ __nv_bfloat16 g_c1lo[(size_t)B1_CNT * 1024];
__device__ __nv_bfloat16 g_w1hi[1024 * D_DIM];             // w1 hi [1024,512]
__device__ __nv_bfloat16 g_w1lo[1024 * D_DIM];

typedef unsigned long long u64t;

// ================= baseline-PTX helpers (compute_103-safe) =================
__device__ __forceinline__ uint32_t smem_u32(const void* p) {
    uint32_t a;
    asm("{ .reg .u64 t; cvta.to.shared.u64 t, %1; cvt.u32.u64 %0, t; }" : "=r"(a) : "l"(p));
    return a;
}
#define CP_ASYNC16(sm, gm) asm volatile("cp.async.cg.shared.global [%0], [%1], 16;" :: "r"(sm), "l"(gm) : "memory")
#define CP_COMMIT()        asm volatile("cp.async.commit_group;" ::: "memory")
#define CP_WAIT1()         asm volatile("cp.async.wait_group 1;" ::: "memory")

__device__ __forceinline__ void ldsm_x4(uint32_t* r, uint32_t addr) {
    asm volatile("ldmatrix.sync.aligned.m8n8.x4.shared.b16 {%0,%1,%2,%3}, [%4];"
        : "=r"(r[0]), "=r"(r[1]), "=r"(r[2]), "=r"(r[3]) : "r"(addr));
}
__device__ __forceinline__ void ldsm_x4_t(uint32_t* r, uint32_t addr) {
    asm volatile("ldmatrix.sync.aligned.m8n8.x4.trans.shared.b16 {%0,%1,%2,%3}, [%4];"
        : "=r"(r[0]), "=r"(r[1]), "=r"(r[2]), "=r"(r[3]) : "r"(addr));
}
__device__ __forceinline__ void mma16816(float* d, const uint32_t* a, const uint32_t* b) {
    asm volatile("mma.sync.aligned.m16n8k16.row.col.f32.bf16.bf16.f32 "
        "{%0,%1,%2,%3}, {%4,%5,%6,%7}, {%8,%9}, {%0,%1,%2,%3};"
        : "+f"(d[0]), "+f"(d[1]), "+f"(d[2]), "+f"(d[3])
        : "r"(a[0]), "r"(a[1]), "r"(a[2]), "r"(a[3]), "r"(b[0]), "r"(b[1]));
}
__device__ __forceinline__ uint32_t pack_bf2(__nv_bfloat16 a, __nv_bfloat16 b) {
    __nv_bfloat162 t = __halves2bfloat162(a, b);
    return *reinterpret_cast<uint32_t*>(&t);
}
__device__ __forceinline__ void split_bf(float f, __nv_bfloat16& hi, __nv_bfloat16& lo) {
    hi = __float2bfloat16(f);
    lo = __float2bfloat16(f - __bfloat162float(hi));
}

// ---------------- packed f32x2 helpers (layer-2 path) ----------------
__device__ __forceinline__ u64t pack_dup(float a) {
    u64t r; asm("mov.b64 %0, {%1, %1};" : "=l"(r) : "f"(a)); return r;
}
__device__ __forceinline__ void fma2(u64t& d, u64t a, u64t b) {
    asm("fma.rn.f32x2 %0, %1, %2, %0;" : "+l"(d) : "l"(a), "l"(b));
}
__device__ __forceinline__ float2 unpack2(u64t v) {
    float lo, hi; asm("mov.b64 {%0, %1}, %2;" : "=f"(lo), "=f"(hi) : "l"(v));
    return make_float2(lo, hi);
}

// ================= small kernels =================
__global__ void build_gidx_kernel(const int* __restrict__ src_nodes,
                                  const int* __restrict__ src_idx1,
                                  int* __restrict__ out, int n) {
    int k = blockIdx.x * blockDim.x + threadIdx.x;
    if (k < n) out[k] = src_nodes[src_idx1[k]];
}

__global__ void gather_cat_kernel(const float* __restrict__ src,
                                  const int* __restrict__ idx,
                                  const int* __restrict__ map,
                                  float* __restrict__ cat) {
    int b = blockIdx.x;
    int r = idx[b];
    if (map) r = map[r];
    const float4* s = reinterpret_cast<const float4*>(src + (size_t)r * 512);
    float4* d = reinterpret_cast<float4*>(cat + (size_t)b * 1024 + 512);
    d[threadIdx.x] = s[threadIdx.x];
}

// generic fp32 -> bf16 hi/lo elementwise split (8 elems / thread)
__global__ void split_kernel(const float* __restrict__ src,
                             __nv_bfloat16* __restrict__ hi,
                             __nv_bfloat16* __restrict__ lo, int n8) {
    int i = blockIdx.x * blockDim.x + threadIdx.x;
    if (i >= n8) return;
    const float4* s = reinterpret_cast<const float4*>(src) + 2 * (size_t)i;
    float4 a = s[0], b = s[1];
    float f[8] = {a.x, a.y, a.z, a.w, b.x, b.y, b.z, b.w};
    __nv_bfloat16 h[8], l[8];
#pragma unroll
    for (int q = 0; q < 8; ++q) split_bf(f[q], h[q], l[q]);
    uint4 hv = make_uint4(pack_bf2(h[0], h[1]), pack_bf2(h[2], h[3]),
                          pack_bf2(h[4], h[5]), pack_bf2(h[6], h[7]));
    uint4 lv = make_uint4(pack_bf2(l[0], l[1]), pack_bf2(l[2], l[3]),
                          pack_bf2(l[4], l[5]), pack_bf2(l[6], l[7]));
    reinterpret_cast<uint4*>(hi)[i] = hv;
    reinterpret_cast<uint4*>(lo)[i] = lv;
}

// gather + split, row-major: X[k][:] = features[gidx[k]][:]
__global__ void prep_x_kernel(const float* __restrict__ features,
                              const int* __restrict__ gidx,
                              __nv_bfloat16* __restrict__ xhi,
                              __nv_bfloat16* __restrict__ xlo) {
    const int k = blockIdx.x;
    const int r = gidx[k];
    float4 v = reinterpret_cast<const float4*>(features + (size_t)r * F_DIM)[threadIdx.x];
    __nv_bfloat16 h0, h1, h2, h3, l0, l1, l2, l3;
    split_bf(v.x, h0, l0); split_bf(v.y, h1, l1);
    split_bf(v.z, h2, l2); split_bf(v.w, h3, l3);
    uint2 hv = make_uint2(pack_bf2(h0, h1), pack_bf2(h2, h3));
    uint2 lv = make_uint2(pack_bf2(l0, l1), pack_bf2(l2, l3));
    reinterpret_cast<uint2*>(xhi + (size_t)k * F_DIM)[threadIdx.x] = hv;
    reinterpret_cast<uint2*>(xlo + (size_t)k * F_DIM)[threadIdx.x] = lv;
}

// ================= HMMA bf16 3-term GEMM (all-async, 3 stages) =================
// C[M,128-col panels] = A @ B, A/B pre-split bf16 hi/lo. BM=BN=128, BK=64.
#define A_TILE_B 16384              // 128 rows x 128B
#define B_TILE_B 16384              // 64 rows x 256B
#define STAGE_B  (2 * A_TILE_B + 2 * B_TILE_B)   // 64KB
#define GSMEM    (3 * STAGE_B)                    // 192KB

template<int KTOT, int LDA, int LDB, int LDC, bool RELU>
__global__ __launch_bounds__(256, 1)
void gemm_hmma(const __nv_bfloat16* __restrict__ Ahi,
               const __nv_bfloat16* __restrict__ Alo,
               const __nv_bfloat16* __restrict__ Bhi,
               const __nv_bfloat16* __restrict__ Blo,
               float* __restrict__ C) {
    constexpr int NCHUNK = KTOT / 64;
    extern __shared__ __align__(128) char smem[];
    const uint32_t sb = smem_u32(smem);
    const int tid = threadIdx.x;
    const int wid = tid >> 5;
    const int lane = tid & 31;
    const int bm = blockIdx.y * 128;
    const int bn = blockIdx.x * 128;
    const int wm = (wid & 3) * 32;
    const int wn = (wid >> 2) * 64;

    float acc[2][8][4];
#pragma unroll
    for (int m = 0; m < 2; ++m)
#pragma unroll
        for (int n = 0; n < 8; ++n)
#pragma unroll
            for (int j = 0; j < 4; ++j) acc[m][n][j] = 0.f;

#define G_LOAD(ch, stg) do {                                                  \
    if ((ch) < NCHUNK) {                                                      \
        size_t k0 = (size_t)(ch) * 64;                                        \
        uint32_t sa = sb + (uint32_t)(stg) * STAGE_B;                         \
        uint32_t sB = sa + 2 * A_TILE_B;                                      \
        _Pragma("unroll")                                                     \
        for (int i = 0; i < 4; ++i) {                                         \
            int lin = tid + i * 256;                                          \
            int row = lin >> 3, seg = lin & 7;                                \
            uint32_t d = sa + row * 128 + (((seg ^ (row & 7))) << 4);         \
            const __nv_bfloat16* gh = Ahi + (size_t)(bm + row) * LDA + k0 + seg * 8; \
            const __nv_bfloat16* gl = Alo + (size_t)(bm + row) * LDA + k0 + seg * 8; \
            CP_ASYNC16(d, gh);                                                \
            CP_ASYNC16(d + A_TILE_B, gl);                                     \
        }                                                                     \
        _Pragma("unroll")                                                     \
        for (int i = 0; i < 4; ++i) {                                         \
            int lin = tid + i * 256;                                          \
            int row = lin >> 4, chk = lin & 15;                               \
            uint32_t d = sB + row * 256 + (((chk ^ (row & 7))) << 4);         \
            const __nv_bfloat16* gh = Bhi + (size_t)(k0 + row) * LDB + bn + chk * 8; \
            const __nv_bfloat16* gl = Blo + (size_t)(k0 + row) * LDB + bn + chk * 8; \
            CP_ASYNC16(d, gh);                                                \
            CP_ASYNC16(d + B_TILE_B, gl);                                     \
        }                                                                     \
    }                                                                         \
    CP_COMMIT();                                                              \
} while (0)

    // prologue: stages 0,1
    G_LOAD(0, 0);
    G_LOAD(1, 1);

    int stg = 0;
    for (int ch = 0; ch < NCHUNK; ++ch) {
        CP_WAIT1();
        __syncthreads();
        G_LOAD(ch + 2, (stg + 2 >= 3) ? (stg - 1) : (stg + 2));

        const uint32_t abase = sb + (uint32_t)stg * STAGE_B;
        const uint32_t bbase = abase + 2 * A_TILE_B;
#pragma unroll
        for (int kk = 0; kk < 4; ++kk) {
            uint32_t ah[2][4], al[2][4];
#pragma unroll
            for (int m = 0; m < 2; ++m) {
                uint32_t r = wm + m * 16 + (lane & 15);
                uint32_t chunk = kk * 2 + (lane >> 4);
                uint32_t ad = abase + r * 128 + ((chunk ^ (r & 7)) << 4);
                ldsm_x4(ah[m], ad);
                ldsm_x4(al[m], ad + A_TILE_B);
            }
            uint32_t bh[4][4], bl[4][4];
#pragma unroll
            for (int j = 0; j < 4; ++j) {
                uint32_t krow = kk * 16 + (lane & 15);
                uint32_t chk = (uint32_t)(wn >> 3) + j * 2 + (lane >> 4);
                uint32_t bd = bbase + krow * 256 + ((chk ^ (krow & 7)) << 4);
                ldsm_x4_t(bh[j], bd);
                ldsm_x4_t(bl[j], bd + B_TILE_B);
            }
#pragma unroll
            for (int m = 0; m < 2; ++m)
#pragma unroll
                for (int j = 0; j < 4; ++j)
#pragma unroll
                    for (int h = 0; h < 2; ++h) {
                        const int n8 = j * 2 + h;
                        mma16816(acc[m][n8], ah[m], &bh[j][2 * h]);
                        mma16816(acc[m][n8], ah[m], &bl[j][2 * h]);
                        mma16816(acc[m][n8], al[m], &bh[j][2 * h]);
                    }
        }
        stg = (stg + 1 == 3) ? 0 : stg + 1;
    }

    // epilogue
#pragma unroll
    for (int m = 0; m < 2; ++m) {
        const int row = bm + wm + m * 16 + (lane >> 2);
#pragma unroll
        for (int n8 = 0; n8 < 8; ++n8) {
            const int col = bn + wn + n8 * 8 + (lane & 3) * 2;
            float2 v0 = make_float2(acc[m][n8][0], acc[m][n8][1]);
            float2 v1 = make_float2(acc[m][n8][2], acc[m][n8][3]);
            if (RELU) {
                v0.x = fmaxf(v0.x, 0.f); v0.y = fmaxf(v0.y, 0.f);
                v1.x = fmaxf(v1.x, 0.f); v1.y = fmaxf(v1.y, 0.f);
            }
            *reinterpret_cast<float2*>(C + (size_t)row * LDC + col) = v0;
            *reinterpret_cast<float2*>(C + (size_t)(row + 8) * LDC + col) = v1;
        }
    }
#undef G_LOAD
}

// ================= f32x2 SGEMM (layer-2 small GEMMs) =================
template<int BMt, int BNt, int BKt, int TM, int TN, bool GATHER_B, bool RELU>
__global__ __launch_bounds__((BMt / TM) * (BNt / TN))
void sgemm_kernel(int M, int N, int K,
                  const float* __restrict__ Am, int lda,
                  const float* __restrict__ Bm, int ldb,
                  const int* __restrict__ bidx,
                  float* __restrict__ Cm, int ldc) {
    constexpr int THREADS = (BMt / TM) * (BNt / TN);
    __shared__ __align__(16) float As[BKt][BMt];
    __shared__ __align__(16) float Bs[BKt][BNt];

    const int tid = threadIdx.x;
    const int block_m = blockIdx.y * BMt;
    const int block_n = blockIdx.x * BNt;
    const int tn = (tid % (BNt / TN)) * TN;
    const int tm = (tid / (BNt / TN)) * TM;

    u64t acc2[TM][TN / 2];
#pragma unroll
    for (int i = 0; i < TM; ++i)
#pragma unroll
        for (int j = 0; j < TN / 2; ++j) acc2[i][j] = 0ull;

    constexpr int LA = (BMt * BKt) / (4 * THREADS);
    constexpr int LB = (BKt * BNt) / (4 * THREADS);
    constexpr int A_F4_PER_ROW = BKt / 4;
    constexpr int B_F4_PER_ROW = BNt / 4;

    for (int k0 = 0; k0 < K; k0 += BKt) {
#pragma unroll
        for (int i = 0; i < LA; ++i) {
            int idx = tid + i * THREADS;
            int row = idx / A_F4_PER_ROW;
            int c4  = idx % A_F4_PER_ROW;
            float4 v = *reinterpret_cast<const float4*>(
                Am + (size_t)(block_m + row) * lda + k0 + c4 * 4);
            As[c4 * 4 + 0][row] = v.x;
            As[c4 * 4 + 1][row] = v.y;
            As[c4 * 4 + 2][row] = v.z;
            As[c4 * 4 + 3][row] = v.w;
        }
#pragma unroll
        for (int i = 0; i < LB; ++i) {
            int idx = tid + i * THREADS;
            int row = idx / B_F4_PER_ROW;
            int c4  = idx % B_F4_PER_ROW;
            const float* brow;
            if (GATHER_B) brow = Bm + (size_t)bidx[k0 + row] * ldb;
            else          brow = Bm + (size_t)(k0 + row) * ldb;
            float4 v = *reinterpret_cast<const float4*>(brow + block_n + c4 * 4);
            *reinterpret_cast<float4*>(&Bs[row][c4 * 4]) = v;
        }
        __syncthreads();
#pragma unroll
        for (int kk = 0; kk < BKt; ++kk) {
            u64t b2[TN / 2];
            const u64t* bs2 = reinterpret_cast<const u64t*>(&Bs[kk][tn]);
#pragma unroll
            for (int j = 0; j < TN / 2; ++j) b2[j] = bs2[j];
#pragma unroll
            for (int i = 0; i < TM; ++i) {
                u64t a2 = pack_dup(As[kk][tm + i]);
#pragma unroll
                for (int j = 0; j < TN / 2; ++j) fma2(acc2[i][j], a2, b2[j]);
            }
        }
        __syncthreads();
    }
#pragma unroll
    for (int i = 0; i < TM; ++i) {
        float* crow = Cm + (size_t)(block_m + tm + i) * ldc + block_n + tn;
#pragma unroll
        for (int j = 0; j < TN / 2; j += 2) {
            float2 v0 = unpack2(acc2[i][j]);
            float2 v1 = unpack2(acc2[i][j + 1]);
            float4 o;
            if (RELU) {
                o.x = fmaxf(v0.x, 0.f); o.y = fmaxf(v0.y, 0.f);
                o.z = fmaxf(v1.x, 0.f); o.w = fmaxf(v1.y, 0.f);
            } else {
                o.x = v0.x; o.y = v0.y; o.z = v1.x; o.w = v1.y;
            }
            *reinterpret_cast<float4*>(crow + j * 2) = o;
        }
    }
}

// ================= classifier + softmax =================
__global__ void cls_softmax_kernel(const float* __restrict__ h2,
                                   const float* __restrict__ wc,
                                   float* __restrict__ out) {
    __shared__ float sh[D_DIM];
    __shared__ float red[C_DIM];
    const int b = blockIdx.x;
    const int c = threadIdx.x;
    for (int i = c; i < D_DIM; i += C_DIM) sh[i] = h2[(size_t)b * D_DIM + i];
    __syncthreads();
    float acc = 0.f;
#pragma unroll 8
    for (int k = 0; k < D_DIM; ++k)
        acc = fmaf(sh[k], wc[(size_t)k * C_DIM + c], acc);
    red[c] = acc;
    __syncthreads();
    for (int s = C_DIM / 2; s > 0; s >>= 1) {
        if (c < s) red[c] = fmaxf(red[c], red[c + s]);
        __syncthreads();
    }
    float mx = red[0];
    __syncthreads();
    float e = expf(acc - mx);
    red[c] = e;
    __syncthreads();
    for (int s = C_DIM / 2; s > 0; s >>= 1) {
        if (c < s) red[c] += red[c + s];
        __syncthreads();
    }
    out[(size_t)b * C_DIM + c] = e / red[0];
}

// ================= launch =================
extern "C" void kernel_launch(void* const* d_in, const int* in_sizes, int n_in,
                              void* d_out, int out_size) {
    const float* features  = (const float*)d_in[0];
    const int*   src_nodes = (const int*)d_in[1];
    const int*   dst_idx1  = (const int*)d_in[2];
    const int*   src_idx1  = (const int*)d_in[3];
    const float* dif_mat1  = (const float*)d_in[4];
    const int*   dst_idx2  = (const int*)d_in[5];
    const int*   src_idx2  = (const int*)d_in[6];
    const float* dif_mat2  = (const float*)d_in[7];
    const float* w1        = (const float*)d_in[8];
    const float* w2        = (const float*)d_in[9];
    const float* w_cls     = (const float*)d_in[10];
    float* out = (float*)d_out;

    float *cat1, *h1, *cat2, *h2;
    int* gidx1;
    __nv_bfloat16 *ahi, *alo, *xhi, *xlo, *c1hi, *c1lo, *w1hi, *w1lo;
    cudaGetSymbolAddress((void**)&cat1,  g_cat1);
    cudaGetSymbolAddress((void**)&h1,    g_h1);
    cudaGetSymbolAddress((void**)&cat2,  g_cat2);
    cudaGetSymbolAddress((void**)&h2,    g_h2);
    cudaGetSymbolAddress((void**)&gidx1, g_gidx1);
    cudaGetSymbolAddress((void**)&ahi,   g_ahi);
    cudaGetSymbolAddress((void**)&alo,   g_alo);
    cudaGetSymbolAddress((void**)&xhi,   g_xhi);
    cudaGetSymbolAddress((void**)&xlo,   g_xlo);
    cudaGetSymbolAddress((void**)&c1hi,  g_c1hi);
    cudaGetSymbolAddress((void**)&c1lo,  g_c1lo);
    cudaGetSymbolAddress((void**)&w1hi,  g_w1hi);
    cudaGetSymbolAddress((void**)&w1lo,  g_w1lo);

    cudaFuncSetAttribute((const void*)gemm_hmma<S1_CNT, S1_CNT, F_DIM, 1024, false>,
                         cudaFuncAttributeMaxDynamicSharedMemorySize, GSMEM);
    cudaFuncSetAttribute((const void*)gemm_hmma<1024, 1024, D_DIM, D_DIM, true>,
                         cudaFuncAttributeMaxDynamicSharedMemorySize, GSMEM);

    // 0) composed gather index + dst gather + splits
    build_gidx_kernel<<<(S1_CNT + 255) / 256, 256>>>(src_nodes, src_idx1, gidx1, S1_CNT);
    gather_cat_kernel<<<B1_CNT, 128>>>(features, dst_idx1, src_nodes, cat1);
    prep_x_kernel<<<S1_CNT, 128>>>(features, gidx1, xhi, xlo);
    {   // split dif_mat1 -> ahi/alo
        int n8 = (B1_CNT * S1_CNT) / 8;
        split_kernel<<<n8 / 256, 256>>>(dif_mat1, ahi, alo, n8);
    }

    // 1) agg1 = dif_mat1 @ X -> cat1[:, 0:512]
    gemm_hmma<S1_CNT, S1_CNT, F_DIM, 1024, false>
        <<<dim3(F_DIM / 128, B1_CNT / 128), 256, GSMEM>>>(ahi, alo, xhi, xlo, cat1);

    // 2) split cat1 and w1, then h1 = relu(cat1 @ w1)
    {
        int n8 = (B1_CNT * 1024) / 8;
        split_kernel<<<n8 / 256, 256>>>(cat1, c1hi, c1lo, n8);
        int m8 = (1024 * D_DIM) / 8;
        split_kernel<<<m8 / 256, 256>>>(w1, w1hi, w1lo, m8);
    }
    gemm_hmma<1024, 1024, D_DIM, D_DIM, true>
        <<<dim3(D_DIM / 128, B1_CNT / 128), 256, GSMEM>>>(c1hi, c1lo, w1hi, w1lo, h1);

    // 3) layer 2 (small): gather, agg2, h2
    gather_cat_kernel<<<B2_CNT, 128>>>(h1, dst_idx2, nullptr, cat2);
    sgemm_kernel<64, 64, 16, 4, 4, true, false>
        <<<dim3(D_DIM / 64, B2_CNT / 64), 256>>>(
            B2_CNT, D_DIM, S2_CNT, dif_mat2, S2_CNT, h1, D_DIM, src_idx2, cat2, 1024);
    sgemm_kernel<64, 64, 16, 4, 4, false, true>
        <<<dim3(D_DIM / 64, B2_CNT / 64), 256>>>(
            B2_CNT, D_DIM, 2 * D_DIM, cat2, 1024, w2, D_DIM, nullptr, h2, D_DIM);

    // 4) out = softmax(h2 @ w_cls)
    cls_softmax_kernel<<<B2_CNT, C_DIM>>>(h2, w_cls, out);
}

// round 5
// speedup vs baseline: 4.2078x; 1.2773x over previous
#include <cuda_runtime.h>
#include <cuda_bf16.h>
#include <cuda_fp16.h>
#include <cstdint>
#include <math.h>

// ---------------- problem constants ----------------
#define V_NODES 100000
#define F_DIM   512
#define D_DIM   512
#define C_DIM   128
#define N1_CNT  36864
#define S1_CNT  32768
#define B1_CNT  4096
#define S2_CNT  3584
#define B2_CNT  512

#define A_SCALE 32768.0f
#define A_INV   (1.0f / 32768.0f)

// ---------------- scratch (device globals; no allocation allowed) ----------------
__device__ float g_cat1[B1_CNT * 1024];
__device__ float g_h1  [B1_CNT * D_DIM];
__device__ float g_cat2[B2_CNT * 1024];
__device__ float g_h2  [B2_CNT * D_DIM];
__device__ int   g_gidx1[S1_CNT];
__device__ __half g_a16[(size_t)B1_CNT * S1_CNT];          // dif_mat1 * 2^15, fp16
__device__ __half g_xhi[(size_t)S1_CNT * F_DIM];           // X hi fp16 [32768,512]
__device__ __half g_xlo[(size_t)S1_CNT * F_DIM];           // X lo fp16
__device__ __nv_bfloat16 g_c1hi[(size_t)B1_CNT * 1024];    // cat1 hi bf16
__device__ __nv_bfloat16 g_c1lo[(size_t)B1_CNT * 1024];
__device__ __nv_bfloat16 g_w1hi[1024 * D_DIM];
__device__ __nv_bfloat16 g_w1lo[1024 * D_DIM];

typedef unsigned long long u64t;

// ================= baseline-PTX helpers (compute_103-safe) =================
__device__ __forceinline__ uint32_t smem_u32(const void* p) {
    uint32_t a;
    asm("{ .reg .u64 t; cvta.to.shared.u64 t, %1; cvt.u32.u64 %0, t; }" : "=r"(a) : "l"(p));
    return a;
}
#define CP_ASYNC16(sm, gm) asm volatile("cp.async.cg.shared.global [%0], [%1], 16;" :: "r"(sm), "l"(gm) : "memory")
#define CP_COMMIT()        asm volatile("cp.async.commit_group;" ::: "memory")
#define CP_WAIT1()         asm volatile("cp.async.wait_group 1;" ::: "memory")
#define CP_WAIT2()         asm volatile("cp.async.wait_group 2;" ::: "memory")

__device__ __forceinline__ void ldsm_x4(uint32_t* r, uint32_t addr) {
    asm volatile("ldmatrix.sync.aligned.m8n8.x4.shared.b16 {%0,%1,%2,%3}, [%4];"
        : "=r"(r[0]), "=r"(r[1]), "=r"(r[2]), "=r"(r[3]) : "r"(addr));
}
__device__ __forceinline__ void ldsm_x4_t(uint32_t* r, uint32_t addr) {
    asm volatile("ldmatrix.sync.aligned.m8n8.x4.trans.shared.b16 {%0,%1,%2,%3}, [%4];"
        : "=r"(r[0]), "=r"(r[1]), "=r"(r[2]), "=r"(r[3]) : "r"(addr));
}
__device__ __forceinline__ void mma_bf16(float* d, const uint32_t* a, const uint32_t* b) {
    asm volatile("mma.sync.aligned.m16n8k16.row.col.f32.bf16.bf16.f32 "
        "{%0,%1,%2,%3}, {%4,%5,%6,%7}, {%8,%9}, {%0,%1,%2,%3};"
        : "+f"(d[0]), "+f"(d[1]), "+f"(d[2]), "+f"(d[3])
        : "r"(a[0]), "r"(a[1]), "r"(a[2]), "r"(a[3]), "r"(b[0]), "r"(b[1]));
}
__device__ __forceinline__ void mma_f16(float* d, const uint32_t* a, const uint32_t* b) {
    asm volatile("mma.sync.aligned.m16n8k16.row.col.f32.f16.f16.f32 "
        "{%0,%1,%2,%3}, {%4,%5,%6,%7}, {%8,%9}, {%0,%1,%2,%3};"
        : "+f"(d[0]), "+f"(d[1]), "+f"(d[2]), "+f"(d[3])
        : "r"(a[0]), "r"(a[1]), "r"(a[2]), "r"(a[3]), "r"(b[0]), "r"(b[1]));
}
__device__ __forceinline__ uint32_t pack_bf2(__nv_bfloat16 a, __nv_bfloat16 b) {
    __nv_bfloat162 t = __halves2bfloat162(a, b);
    return *reinterpret_cast<uint32_t*>(&t);
}
__device__ __forceinline__ uint32_t pack_h2(__half a, __half b) {
    __half2 t = __halves2half2(a, b);
    return *reinterpret_cast<uint32_t*>(&t);
}
__device__ __forceinline__ void split_bf(float f, __nv_bfloat16& hi, __nv_bfloat16& lo) {
    hi = __float2bfloat16(f);
    lo = __float2bfloat16(f - __bfloat162float(hi));
}
__device__ __forceinline__ void split_h(float f, __half& hi, __half& lo) {
    hi = __float2half(f);
    lo = __float2half(f - __half2float(hi));
}

// ---------------- packed f32x2 helpers (layer-2 path) ----------------
__device__ __forceinline__ u64t pack_dup(float a) {
    u64t r; asm("mov.b64 %0, {%1, %1};" : "=l"(r) : "f"(a)); return r;
}
__device__ __forceinline__ void fma2(u64t& d, u64t a, u64t b) {
    asm("fma.rn.f32x2 %0, %1, %2, %0;" : "+l"(d) : "l"(a), "l"(b));
}
__device__ __forceinline__ float2 unpack2(u64t v) {
    float lo, hi; asm("mov.b64 {%0, %1}, %2;" : "=f"(lo), "=f"(hi) : "l"(v));
    return make_float2(lo, hi);
}

// ================= small kernels =================
__global__ void build_gidx_kernel(const int* __restrict__ src_nodes,
                                  const int* __restrict__ src_idx1,
                                  int* __restrict__ out, int n) {
    int k = blockIdx.x * blockDim.x + threadIdx.x;
    if (k < n) out[k] = src_nodes[src_idx1[k]];
}

__global__ void gather_cat_kernel(const float* __restrict__ src,
                                  const int* __restrict__ idx,
                                  const int* __restrict__ map,
                                  float* __restrict__ cat) {
    int b = blockIdx.x;
    int r = idx[b];
    if (map) r = map[r];
    const float4* s = reinterpret_cast<const float4*>(src + (size_t)r * 512);
    float4* d = reinterpret_cast<float4*>(cat + (size_t)b * 1024 + 512);
    d[threadIdx.x] = s[threadIdx.x];
}

// fp32 -> bf16 hi/lo split (8 elems / thread)
__global__ void split_kernel(const float* __restrict__ src,
                             __nv_bfloat16* __restrict__ hi,
                             __nv_bfloat16* __restrict__ lo, int n8) {
    int i = blockIdx.x * blockDim.x + threadIdx.x;
    if (i >= n8) return;
    const float4* s = reinterpret_cast<const float4*>(src) + 2 * (size_t)i;
    float4 a = s[0], b = s[1];
    float f[8] = {a.x, a.y, a.z, a.w, b.x, b.y, b.z, b.w};
    __nv_bfloat16 h[8], l[8];
#pragma unroll
    for (int q = 0; q < 8; ++q) split_bf(f[q], h[q], l[q]);
    uint4 hv = make_uint4(pack_bf2(h[0], h[1]), pack_bf2(h[2], h[3]),
                          pack_bf2(h[4], h[5]), pack_bf2(h[6], h[7]));
    uint4 lv = make_uint4(pack_bf2(l[0], l[1]), pack_bf2(l[2], l[3]),
                          pack_bf2(l[4], l[5]), pack_bf2(l[6], l[7]));
    reinterpret_cast<uint4*>(hi)[i] = hv;
    reinterpret_cast<uint4*>(lo)[i] = lv;
}

// fp32 * 2^15 -> fp16 (8 elems / thread)
__global__ void scale_f16_kernel(const float* __restrict__ src,
                                 __half* __restrict__ dst, int n8) {
    int i = blockIdx.x * blockDim.x + threadIdx.x;
    if (i >= n8) return;
    const float4* s = reinterpret_cast<const float4*>(src) + 2 * (size_t)i;
    float4 a = s[0], b = s[1];
    float f[8] = {a.x, a.y, a.z, a.w, b.x, b.y, b.z, b.w};
    __half h[8];
#pragma unroll
    for (int q = 0; q < 8; ++q) h[q] = __float2half(f[q] * A_SCALE);
    uint4 v = make_uint4(pack_h2(h[0], h[1]), pack_h2(h[2], h[3]),
                         pack_h2(h[4], h[5]), pack_h2(h[6], h[7]));
    reinterpret_cast<uint4*>(dst)[i] = v;
}

// gather + fp16 hi/lo split: X[k][:] = features[gidx[k]][:]
__global__ void prep_x_kernel(const float* __restrict__ features,
                              const int* __restrict__ gidx,
                              __half* __restrict__ xhi,
                              __half* __restrict__ xlo) {
    const int k = blockIdx.x;
    const int r = gidx[k];
    float4 v = reinterpret_cast<const float4*>(features + (size_t)r * F_DIM)[threadIdx.x];
    __half h0, h1, h2, h3, l0, l1, l2, l3;
    split_h(v.x, h0, l0); split_h(v.y, h1, l1);
    split_h(v.z, h2, l2); split_h(v.w, h3, l3);
    uint2 hv = make_uint2(pack_h2(h0, h1), pack_h2(h2, h3));
    uint2 lv = make_uint2(pack_h2(l0, l1), pack_h2(l2, l3));
    reinterpret_cast<uint2*>(xhi + (size_t)k * F_DIM)[threadIdx.x] = hv;
    reinterpret_cast<uint2*>(xlo + (size_t)k * F_DIM)[threadIdx.x] = lv;
}

// ================= GEMM1: fp16 2-term, A single, 4-stage pipeline =================
// C[4096,512] = (A16/2^15) @ (Xhi+Xlo). BM=BN=128, BK=64.
#define F_A_TILE 16384              // 128 rows x 128B (64 fp16)
#define F_B_TILE 16384              // 64 rows x 256B (128 fp16)
#define F_STAGE  (F_A_TILE + 2 * F_B_TILE)   // 48KB
#define F_SMEM   (4 * F_STAGE)               // 192KB

__global__ __launch_bounds__(256, 1)
void gemm1_f16(const __half* __restrict__ A,
               const __half* __restrict__ Bhi,
               const __half* __restrict__ Blo,
               float* __restrict__ C) {
    constexpr int NCHUNK = S1_CNT / 64;
    constexpr int LDA = S1_CNT, LDB = F_DIM, LDC = 1024;
    extern __shared__ __align__(128) char smem[];
    const uint32_t sb = smem_u32(smem);
    const int tid = threadIdx.x;
    const int wid = tid >> 5;
    const int lane = tid & 31;
    const int bm = blockIdx.y * 128;
    const int bn = blockIdx.x * 128;
    const int wm = (wid & 3) * 32;
    const int wn = (wid >> 2) * 64;

    float acc[2][8][4];
#pragma unroll
    for (int m = 0; m < 2; ++m)
#pragma unroll
        for (int n = 0; n < 8; ++n)
#pragma unroll
            for (int j = 0; j < 4; ++j) acc[m][n][j] = 0.f;

#define F_LOAD(ch) do {                                                       \
    if ((ch) < NCHUNK) {                                                      \
        size_t k0 = (size_t)(ch) * 64;                                        \
        uint32_t sa = sb + (uint32_t)((ch) & 3) * F_STAGE;                    \
        uint32_t sB = sa + F_A_TILE;                                          \
        _Pragma("unroll")                                                     \
        for (int i = 0; i < 4; ++i) {                                         \
            int lin = tid + i * 256;                                          \
            int row = lin >> 3, seg = lin & 7;                                \
            uint32_t d = sa + row * 128 + (((seg ^ (row & 7))) << 4);         \
            CP_ASYNC16(d, A + (size_t)(bm + row) * LDA + k0 + seg * 8);       \
        }                                                                     \
        _Pragma("unroll")                                                     \
        for (int i = 0; i < 4; ++i) {                                         \
            int lin = tid + i * 256;                                          \
            int row = lin >> 4, chk = lin & 15;                               \
            uint32_t d = sB + row * 256 + (((chk ^ (row & 7))) << 4);         \
            CP_ASYNC16(d, Bhi + (size_t)(k0 + row) * LDB + bn + chk * 8);     \
            CP_ASYNC16(d + F_B_TILE, Blo + (size_t)(k0 + row) * LDB + bn + chk * 8); \
        }                                                                     \
    }                                                                         \
    CP_COMMIT();                                                              \
} while (0)

    F_LOAD(0); F_LOAD(1); F_LOAD(2);

    for (int ch = 0; ch < NCHUNK; ++ch) {
        CP_WAIT2();
        __syncthreads();
        F_LOAD(ch + 3);

        const uint32_t abase = sb + (uint32_t)(ch & 3) * F_STAGE;
        const uint32_t bbase = abase + F_A_TILE;
#pragma unroll
        for (int kk = 0; kk < 4; ++kk) {
            uint32_t ah[2][4];
#pragma unroll
            for (int m = 0; m < 2; ++m) {
                uint32_t r = wm + m * 16 + (lane & 15);
                uint32_t chunk = kk * 2 + (lane >> 4);
                ldsm_x4(ah[m], abase + r * 128 + ((chunk ^ (r & 7)) << 4));
            }
            uint32_t bh[4][4], bl[4][4];
#pragma unroll
            for (int j = 0; j < 4; ++j) {
                uint32_t krow = kk * 16 + (lane & 15);
                uint32_t chk = (uint32_t)(wn >> 3) + j * 2 + (lane >> 4);
                uint32_t bd = bbase + krow * 256 + ((chk ^ (krow & 7)) << 4);
                ldsm_x4_t(bh[j], bd);
                ldsm_x4_t(bl[j], bd + F_B_TILE);
            }
#pragma unroll
            for (int m = 0; m < 2; ++m)
#pragma unroll
                for (int j = 0; j < 4; ++j)
#pragma unroll
                    for (int h = 0; h < 2; ++h) {
                        const int n8 = j * 2 + h;
                        mma_f16(acc[m][n8], ah[m], &bh[j][2 * h]);
                        mma_f16(acc[m][n8], ah[m], &bl[j][2 * h]);
                    }
        }
        __syncthreads();
    }

#pragma unroll
    for (int m = 0; m < 2; ++m) {
        const int row = bm + wm + m * 16 + (lane >> 2);
#pragma unroll
        for (int n8 = 0; n8 < 8; ++n8) {
            const int col = bn + wn + n8 * 8 + (lane & 3) * 2;
            *reinterpret_cast<float2*>(C + (size_t)row * LDC + col) =
                make_float2(acc[m][n8][0] * A_INV, acc[m][n8][1] * A_INV);
            *reinterpret_cast<float2*>(C + (size_t)(row + 8) * LDC + col) =
                make_float2(acc[m][n8][2] * A_INV, acc[m][n8][3] * A_INV);
        }
    }
#undef F_LOAD
}

// ================= bf16 3-term GEMM (cat1 @ w1), 3-stage =================
#define A_TILE_B 16384
#define B_TILE_B 16384
#define STAGE_B  (2 * A_TILE_B + 2 * B_TILE_B)
#define GSMEM    (3 * STAGE_B)

template<int KTOT, int LDA, int LDB, int LDC, bool RELU>
__global__ __launch_bounds__(256, 1)
void gemm_hmma3(const __nv_bfloat16* __restrict__ Ahi,
                const __nv_bfloat16* __restrict__ Alo,
                const __nv_bfloat16* __restrict__ Bhi,
                const __nv_bfloat16* __restrict__ Blo,
                float* __restrict__ C) {
    constexpr int NCHUNK = KTOT / 64;
    extern __shared__ __align__(128) char smem[];
    const uint32_t sb = smem_u32(smem);
    const int tid = threadIdx.x;
    const int wid = tid >> 5;
    const int lane = tid & 31;
    const int bm = blockIdx.y * 128;
    const int bn = blockIdx.x * 128;
    const int wm = (wid & 3) * 32;
    const int wn = (wid >> 2) * 64;

    float acc[2][8][4];
#pragma unroll
    for (int m = 0; m < 2; ++m)
#pragma unroll
        for (int n = 0; n < 8; ++n)
#pragma unroll
            for (int j = 0; j < 4; ++j) acc[m][n][j] = 0.f;

#define G_LOAD(ch, stg) do {                                                  \
    if ((ch) < NCHUNK) {                                                      \
        size_t k0 = (size_t)(ch) * 64;                                        \
        uint32_t sa = sb + (uint32_t)(stg) * STAGE_B;                         \
        uint32_t sB = sa + 2 * A_TILE_B;                                      \
        _Pragma("unroll")                                                     \
        for (int i = 0; i < 4; ++i) {                                         \
            int lin = tid + i * 256;                                          \
            int row = lin >> 3, seg = lin & 7;                                \
            uint32_t d = sa + row * 128 + (((seg ^ (row & 7))) << 4);         \
            CP_ASYNC16(d, Ahi + (size_t)(bm + row) * LDA + k0 + seg * 8);     \
            CP_ASYNC16(d + A_TILE_B, Alo + (size_t)(bm + row) * LDA + k0 + seg * 8); \
        }                                                                     \
        _Pragma("unroll")                                                     \
        for (int i = 0; i < 4; ++i) {                                         \
            int lin = tid + i * 256;                                          \
            int row = lin >> 4, chk = lin & 15;                               \
            uint32_t d = sB + row * 256 + (((chk ^ (row & 7))) << 4);         \
            CP_ASYNC16(d, Bhi + (size_t)(k0 + row) * LDB + bn + chk * 8);     \
            CP_ASYNC16(d + B_TILE_B, Blo + (size_t)(k0 + row) * LDB + bn + chk * 8); \
        }                                                                     \
    }                                                                         \
    CP_COMMIT();                                                              \
} while (0)

    G_LOAD(0, 0);
    G_LOAD(1, 1);

    int stg = 0;
    for (int ch = 0; ch < NCHUNK; ++ch) {
        CP_WAIT1();
        __syncthreads();
        G_LOAD(ch + 2, (stg + 2 >= 3) ? (stg - 1) : (stg + 2));

        const uint32_t abase = sb + (uint32_t)stg * STAGE_B;
        const uint32_t bbase = abase + 2 * A_TILE_B;
#pragma unroll
        for (int kk = 0; kk < 4; ++kk) {
            uint32_t ah[2][4], al[2][4];
#pragma unroll
            for (int m = 0; m < 2; ++m) {
                uint32_t r = wm + m * 16 + (lane & 15);
                uint32_t chunk = kk * 2 + (lane >> 4);
                uint32_t ad = abase + r * 128 + ((chunk ^ (r & 7)) << 4);
                ldsm_x4(ah[m], ad);
                ldsm_x4(al[m], ad + A_TILE_B);
            }
            uint32_t bh[4][4], bl[4][4];
#pragma unroll
            for (int j = 0; j < 4; ++j) {
                uint32_t krow = kk * 16 + (lane & 15);
                uint32_t chk = (uint32_t)(wn >> 3) + j * 2 + (lane >> 4);
                uint32_t bd = bbase + krow * 256 + ((chk ^ (krow & 7)) << 4);
                ldsm_x4_t(bh[j], bd);
                ldsm_x4_t(bl[j], bd + B_TILE_B);
            }
#pragma unroll
            for (int m = 0; m < 2; ++m)
#pragma unroll
                for (int j = 0; j < 4; ++j)
#pragma unroll
                    for (int h = 0; h < 2; ++h) {
                        const int n8 = j * 2 + h;
                        mma_bf16(acc[m][n8], ah[m], &bh[j][2 * h]);
                        mma_bf16(acc[m][n8], ah[m], &bl[j][2 * h]);
                        mma_bf16(acc[m][n8], al[m], &bh[j][2 * h]);
                    }
        }
        stg = (stg + 1 == 3) ? 0 : stg + 1;
    }

#pragma unroll
    for (int m = 0; m < 2; ++m) {
        const int row = bm + wm + m * 16 + (lane >> 2);
#pragma unroll
        for (int n8 = 0; n8 < 8; ++n8) {
            const int col = bn + wn + n8 * 8 + (lane & 3) * 2;
            float2 v0 = make_float2(acc[m][n8][0], acc[m][n8][1]);
            float2 v1 = make_float2(acc[m][n8][2], acc[m][n8][3]);
            if (RELU) {
                v0.x = fmaxf(v0.x, 0.f); v0.y = fmaxf(v0.y, 0.f);
                v1.x = fmaxf(v1.x, 0.f); v1.y = fmaxf(v1.y, 0.f);
            }
            *reinterpret_cast<float2*>(C + (size_t)row * LDC + col) = v0;
            *reinterpret_cast<float2*>(C + (size_t)(row + 8) * LDC + col) = v1;
        }
    }
#undef G_LOAD
}

// ================= f32x2 SGEMM (layer-2 small GEMMs) =================
template<int BMt, int BNt, int BKt, int TM, int TN, bool GATHER_B, bool RELU>
__global__ __launch_bounds__((BMt / TM) * (BNt / TN))
void sgemm_kernel(int M, int N, int K,
                  const float* __restrict__ Am, int lda,
                  const float* __restrict__ Bm, int ldb,
                  const int* __restrict__ bidx,
                  float* __restrict__ Cm, int ldc) {
    constexpr int THREADS = (BMt / TM) * (BNt / TN);
    __shared__ __align__(16) float As[BKt][BMt];
    __shared__ __align__(16) float Bs[BKt][BNt];

    const int tid = threadIdx.x;
    const int block_m = blockIdx.y * BMt;
    const int block_n = blockIdx.x * BNt;
    const int tn = (tid % (BNt / TN)) * TN;
    const int tm = (tid / (BNt / TN)) * TM;

    u64t acc2[TM][TN / 2];
#pragma unroll
    for (int i = 0; i < TM; ++i)
#pragma unroll
        for (int j = 0; j < TN / 2; ++j) acc2[i][j] = 0ull;

    constexpr int LA = (BMt * BKt) / (4 * THREADS);
    constexpr int LB = (BKt * BNt) / (4 * THREADS);
    constexpr int A_F4_PER_ROW = BKt / 4;
    constexpr int B_F4_PER_ROW = BNt / 4;

    for (int k0 = 0; k0 < K; k0 += BKt) {
#pragma unroll
        for (int i = 0; i < LA; ++i) {
            int idx = tid + i * THREADS;
            int row = idx / A_F4_PER_ROW;
            int c4  = idx % A_F4_PER_ROW;
            float4 v = *reinterpret_cast<const float4*>(
                Am + (size_t)(block_m + row) * lda + k0 + c4 * 4);
            As[c4 * 4 + 0][row] = v.x;
            As[c4 * 4 + 1][row] = v.y;
            As[c4 * 4 + 2][row] = v.z;
            As[c4 * 4 + 3][row] = v.w;
        }
#pragma unroll
        for (int i = 0; i < LB; ++i) {
            int idx = tid + i * THREADS;
            int row = idx / B_F4_PER_ROW;
            int c4  = idx % B_F4_PER_ROW;
            const float* brow;
            if (GATHER_B) brow = Bm + (size_t)bidx[k0 + row] * ldb;
            else          brow = Bm + (size_t)(k0 + row) * ldb;
            float4 v = *reinterpret_cast<const float4*>(brow + block_n + c4 * 4);
            *reinterpret_cast<float4*>(&Bs[row][c4 * 4]) = v;
        }
        __syncthreads();
#pragma unroll
        for (int kk = 0; kk < BKt; ++kk) {
            u64t b2[TN / 2];
            const u64t* bs2 = reinterpret_cast<const u64t*>(&Bs[kk][tn]);
#pragma unroll
            for (int j = 0; j < TN / 2; ++j) b2[j] = bs2[j];
#pragma unroll
            for (int i = 0; i < TM; ++i) {
                u64t a2 = pack_dup(As[kk][tm + i]);
#pragma unroll
                for (int j = 0; j < TN / 2; ++j) fma2(acc2[i][j], a2, b2[j]);
            }
        }
        __syncthreads();
    }
#pragma unroll
    for (int i = 0; i < TM; ++i) {
        float* crow = Cm + (size_t)(block_m + tm + i) * ldc + block_n + tn;
#pragma unroll
        for (int j = 0; j < TN / 2; j += 2) {
            float2 v0 = unpack2(acc2[i][j]);
            float2 v1 = unpack2(acc2[i][j + 1]);
            float4 o;
            if (RELU) {
                o.x = fmaxf(v0.x, 0.f); o.y = fmaxf(v0.y, 0.f);
                o.z = fmaxf(v1.x, 0.f); o.w = fmaxf(v1.y, 0.f);
            } else {
                o.x = v0.x; o.y = v0.y; o.z = v1.x; o.w = v1.y;
            }
            *reinterpret_cast<float4*>(crow + j * 2) = o;
        }
    }
}

// ================= classifier + softmax =================
__global__ void cls_softmax_kernel(const float* __restrict__ h2,
                                   const float* __restrict__ wc,
                                   float* __restrict__ out) {
    __shared__ float sh[D_DIM];
    __shared__ float red[C_DIM];
    const int b = blockIdx.x;
    const int c = threadIdx.x;
    for (int i = c; i < D_DIM; i += C_DIM) sh[i] = h2[(size_t)b * D_DIM + i];
    __syncthreads();
    float acc = 0.f;
#pragma unroll 8
    for (int k = 0; k < D_DIM; ++k)
        acc = fmaf(sh[k], wc[(size_t)k * C_DIM + c], acc);
    red[c] = acc;
    __syncthreads();
    for (int s = C_DIM / 2; s > 0; s >>= 1) {
        if (c < s) red[c] = fmaxf(red[c], red[c + s]);
        __syncthreads();
    }
    float mx = red[0];
    __syncthreads();
    float e = expf(acc - mx);
    red[c] = e;
    __syncthreads();
    for (int s = C_DIM / 2; s > 0; s >>= 1) {
        if (c < s) red[c] += red[c + s];
        __syncthreads();
    }
    out[(size_t)b * C_DIM + c] = e / red[0];
}

// ================= launch =================
extern "C" void kernel_launch(void* const* d_in, const int* in_sizes, int n_in,
                              void* d_out, int out_size) {
    const float* features  = (const float*)d_in[0];
    const int*   src_nodes = (const int*)d_in[1];
    const int*   dst_idx1  = (const int*)d_in[2];
    const int*   src_idx1  = (const int*)d_in[3];
    const float* dif_mat1  = (const float*)d_in[4];
    const int*   dst_idx2  = (const int*)d_in[5];
    const int*   src_idx2  = (const int*)d_in[6];
    const float* dif_mat2  = (const float*)d_in[7];
    const float* w1        = (const float*)d_in[8];
    const float* w2        = (const float*)d_in[9];
    const float* w_cls     = (const float*)d_in[10];
    float* out = (float*)d_out;

    float *cat1, *h1, *cat2, *h2;
    int* gidx1;
    __half *a16, *xhi, *xlo;
    __nv_bfloat16 *c1hi, *c1lo, *w1hi, *w1lo;
    cudaGetSymbolAddress((void**)&cat1,  g_cat1);
    cudaGetSymbolAddress((void**)&h1,    g_h1);
    cudaGetSymbolAddress((void**)&cat2,  g_cat2);
    cudaGetSymbolAddress((void**)&h2,    g_h2);
    cudaGetSymbolAddress((void**)&gidx1, g_gidx1);
    cudaGetSymbolAddress((void**)&a16,   g_a16);
    cudaGetSymbolAddress((void**)&xhi,   g_xhi);
    cudaGetSymbolAddress((void**)&xlo,   g_xlo);
    cudaGetSymbolAddress((void**)&c1hi,  g_c1hi);
    cudaGetSymbolAddress((void**)&c1lo,  g_c1lo);
    cudaGetSymbolAddress((void**)&w1hi,  g_w1hi);
    cudaGetSymbolAddress((void**)&w1lo,  g_w1lo);

    cudaFuncSetAttribute((const void*)gemm1_f16,
                         cudaFuncAttributeMaxDynamicSharedMemorySize, F_SMEM);
    cudaFuncSetAttribute((const void*)gemm_hmma3<1024, 1024, D_DIM, D_DIM, true>,
                         cudaFuncAttributeMaxDynamicSharedMemorySize, GSMEM);

    // 0) index composition, dst gather, operand prep
    build_gidx_kernel<<<(S1_CNT + 255) / 256, 256>>>(src_nodes, src_idx1, gidx1, S1_CNT);
    gather_cat_kernel<<<B1_CNT, 128>>>(features, dst_idx1, src_nodes, cat1);
    prep_x_kernel<<<S1_CNT, 128>>>(features, gidx1, xhi, xlo);
    {   // scaled fp16 A
        int n8 = (B1_CNT * S1_CNT) / 8;
        scale_f16_kernel<<<n8 / 256, 256>>>(dif_mat1, a16, n8);
    }

    // 1) agg1 = dif_mat1 @ X -> cat1[:, 0:512]   (fp16 2-term)
    gemm1_f16<<<dim3(F_DIM / 128, B1_CNT / 128), 256, F_SMEM>>>(a16, xhi, xlo, cat1);

    // 2) split cat1 / w1 (bf16), h1 = relu(cat1 @ w1)  (bf16 3-term)
    {
        int n8 = (B1_CNT * 1024) / 8;
        split_kernel<<<n8 / 256, 256>>>(cat1, c1hi, c1lo, n8);
        int m8 = (1024 * D_DIM) / 8;
        split_kernel<<<m8 / 256, 256>>>(w1, w1hi, w1lo, m8);
    }
    gemm_hmma3<1024, 1024, D_DIM, D_DIM, true>
        <<<dim3(D_DIM / 128, B1_CNT / 128), 256, GSMEM>>>(c1hi, c1lo, w1hi, w1lo, h1);

    // 3) layer 2 (small)
    gather_cat_kernel<<<B2_CNT, 128>>>(h1, dst_idx2, nullptr, cat2);
    sgemm_kernel<64, 64, 16, 4, 4, true, false>
        <<<dim3(D_DIM / 64, B2_CNT / 64), 256>>>(
            B2_CNT, D_DIM, S2_CNT, dif_mat2, S2_CNT, h1, D_DIM, src_idx2, cat2, 1024);
    sgemm_kernel<64, 64, 16, 4, 4, false, true>
        <<<dim3(D_DIM / 64, B2_CNT / 64), 256>>>(
            B2_CNT, D_DIM, 2 * D_DIM, cat2, 1024, w2, D_DIM, nullptr, h2, D_DIM);

    // 4) out = softmax(h2 @ w_cls)
    cls_softmax_kernel<<<B2_CNT, C_DIM>>>(h2, w_cls, out);
}

// round 6
// speedup vs baseline: 5.3842x; 1.2796x over previous
#include <cuda_runtime.h>
#include <cuda_bf16.h>
#include <cuda_fp16.h>
#include <cstdint>
#include <math.h>

// ---------------- problem constants ----------------
#define V_NODES 100000
#define F_DIM   512
#define D_DIM   512
#define C_DIM   128
#define N1_CNT  36864
#define S1_CNT  32768
#define B1_CNT  4096
#define S2_CNT  3584
#define B2_CNT  512

#define A_SCALE 32768.0f
#define A_INV   (1.0f / 32768.0f)

// ---------------- scratch (device globals; no allocation allowed) ----------------
__device__ float g_cat1[B1_CNT * 1024];
__device__ float g_h1  [B1_CNT * D_DIM];
__device__ float g_cat2[B2_CNT * 1024];
__device__ float g_h2  [B2_CNT * D_DIM];
__device__ int   g_gidx1[S1_CNT];
__device__ __half g_a16[(size_t)B1_CNT * S1_CNT];          // dif_mat1 * 2^15, fp16
__device__ __half g_xhi[(size_t)S1_CNT * F_DIM];           // X fp16 [32768,512]
__device__ __nv_bfloat16 g_c1hi[(size_t)B1_CNT * 1024];    // cat1 hi bf16
__device__ __nv_bfloat16 g_c1lo[(size_t)B1_CNT * 1024];
__device__ __nv_bfloat16 g_w1hi[1024 * D_DIM];
__device__ __nv_bfloat16 g_w1lo[1024 * D_DIM];

typedef unsigned long long u64t;

// ================= baseline-PTX helpers (compute_103-safe) =================
__device__ __forceinline__ uint32_t smem_u32(const void* p) {
    uint32_t a;
    asm("{ .reg .u64 t; cvta.to.shared.u64 t, %1; cvt.u32.u64 %0, t; }" : "=r"(a) : "l"(p));
    return a;
}
#define CP_ASYNC16(sm, gm) asm volatile("cp.async.cg.shared.global [%0], [%1], 16;" :: "r"(sm), "l"(gm) : "memory")
#define CP_COMMIT()        asm volatile("cp.async.commit_group;" ::: "memory")
#define CP_WAIT1()         asm volatile("cp.async.wait_group 1;" ::: "memory")
#define CP_WAIT4()         asm volatile("cp.async.wait_group 4;" ::: "memory")

__device__ __forceinline__ void ldsm_x4(uint32_t* r, uint32_t addr) {
    asm volatile("ldmatrix.sync.aligned.m8n8.x4.shared.b16 {%0,%1,%2,%3}, [%4];"
        : "=r"(r[0]), "=r"(r[1]), "=r"(r[2]), "=r"(r[3]) : "r"(addr));
}
__device__ __forceinline__ void ldsm_x4_t(uint32_t* r, uint32_t addr) {
    asm volatile("ldmatrix.sync.aligned.m8n8.x4.trans.shared.b16 {%0,%1,%2,%3}, [%4];"
        : "=r"(r[0]), "=r"(r[1]), "=r"(r[2]), "=r"(r[3]) : "r"(addr));
}
__device__ __forceinline__ void mma_bf16(float* d, const uint32_t* a, const uint32_t* b) {
    asm volatile("mma.sync.aligned.m16n8k16.row.col.f32.bf16.bf16.f32 "
        "{%0,%1,%2,%3}, {%4,%5,%6,%7}, {%8,%9}, {%0,%1,%2,%3};"
        : "+f"(d[0]), "+f"(d[1]), "+f"(d[2]), "+f"(d[3])
        : "r"(a[0]), "r"(a[1]), "r"(a[2]), "r"(a[3]), "r"(b[0]), "r"(b[1]));
}
__device__ __forceinline__ void mma_f16(float* d, const uint32_t* a, const uint32_t* b) {
    asm volatile("mma.sync.aligned.m16n8k16.row.col.f32.f16.f16.f32 "
        "{%0,%1,%2,%3}, {%4,%5,%6,%7}, {%8,%9}, {%0,%1,%2,%3};"
        : "+f"(d[0]), "+f"(d[1]), "+f"(d[2]), "+f"(d[3])
        : "r"(a[0]), "r"(a[1]), "r"(a[2]), "r"(a[3]), "r"(b[0]), "r"(b[1]));
}
__device__ __forceinline__ uint32_t pack_bf2(__nv_bfloat16 a, __nv_bfloat16 b) {
    __nv_bfloat162 t = __halves2bfloat162(a, b);
    return *reinterpret_cast<uint32_t*>(&t);
}
__device__ __forceinline__ uint32_t pack_h2(__half a, __half b) {
    __half2 t = __halves2half2(a, b);
    return *reinterpret_cast<uint32_t*>(&t);
}
__device__ __forceinline__ void split_bf(float f, __nv_bfloat16& hi, __nv_bfloat16& lo) {
    hi = __float2bfloat16(f);
    lo = __float2bfloat16(f - __bfloat162float(hi));
}

// ---------------- packed f32x2 helpers (layer-2 path) ----------------
__device__ __forceinline__ u64t pack_dup(float a) {
    u64t r; asm("mov.b64 %0, {%1, %1};" : "=l"(r) : "f"(a)); return r;
}
__device__ __forceinline__ void fma2(u64t& d, u64t a, u64t b) {
    asm("fma.rn.f32x2 %0, %1, %2, %0;" : "+l"(d) : "l"(a), "l"(b));
}
__device__ __forceinline__ float2 unpack2(u64t v) {
    float lo, hi; asm("mov.b64 {%0, %1}, %2;" : "=f"(lo), "=f"(hi) : "l"(v));
    return make_float2(lo, hi);
}

// ================= small kernels =================
__global__ void build_gidx_kernel(const int* __restrict__ src_nodes,
                                  const int* __restrict__ src_idx1,
                                  int* __restrict__ out, int n) {
    int k = blockIdx.x * blockDim.x + threadIdx.x;
    if (k < n) out[k] = src_nodes[src_idx1[k]];
}

__global__ void gather_cat_kernel(const float* __restrict__ src,
                                  const int* __restrict__ idx,
                                  const int* __restrict__ map,
                                  float* __restrict__ cat) {
    int b = blockIdx.x;
    int r = idx[b];
    if (map) r = map[r];
    const float4* s = reinterpret_cast<const float4*>(src + (size_t)r * 512);
    float4* d = reinterpret_cast<float4*>(cat + (size_t)b * 1024 + 512);
    d[threadIdx.x] = s[threadIdx.x];
}

// fp32 -> bf16 hi/lo split (8 elems / thread)
__global__ void split_kernel(const float* __restrict__ src,
                             __nv_bfloat16* __restrict__ hi,
                             __nv_bfloat16* __restrict__ lo, int n8) {
    int i = blockIdx.x * blockDim.x + threadIdx.x;
    if (i >= n8) return;
    const float4* s = reinterpret_cast<const float4*>(src) + 2 * (size_t)i;
    float4 a = s[0], b = s[1];
    float f[8] = {a.x, a.y, a.z, a.w, b.x, b.y, b.z, b.w};
    __nv_bfloat16 h[8], l[8];
#pragma unroll
    for (int q = 0; q < 8; ++q) split_bf(f[q], h[q], l[q]);
    uint4 hv = make_uint4(pack_bf2(h[0], h[1]), pack_bf2(h[2], h[3]),
                          pack_bf2(h[4], h[5]), pack_bf2(h[6], h[7]));
    uint4 lv = make_uint4(pack_bf2(l[0], l[1]), pack_bf2(l[2], l[3]),
                          pack_bf2(l[4], l[5]), pack_bf2(l[6], l[7]));
    reinterpret_cast<uint4*>(hi)[i] = hv;
    reinterpret_cast<uint4*>(lo)[i] = lv;
}

// fp32 * 2^15 -> fp16 (8 elems / thread)
__global__ void scale_f16_kernel(const float* __restrict__ src,
                                 __half* __restrict__ dst, int n8) {
    int i = blockIdx.x * blockDim.x + threadIdx.x;
    if (i >= n8) return;
    const float4* s = reinterpret_cast<const float4*>(src) + 2 * (size_t)i;
    float4 a = s[0], b = s[1];
    float f[8] = {a.x, a.y, a.z, a.w, b.x, b.y, b.z, b.w};
    __half h[8];
#pragma unroll
    for (int q = 0; q < 8; ++q) h[q] = __float2half(f[q] * A_SCALE);
    uint4 v = make_uint4(pack_h2(h[0], h[1]), pack_h2(h[2], h[3]),
                         pack_h2(h[4], h[5]), pack_h2(h[6], h[7]));
    reinterpret_cast<uint4*>(dst)[i] = v;
}

// gather + fp16 convert: X[k][:] = features[gidx[k]][:]
__global__ void prep_x_kernel(const float* __restrict__ features,
                              const int* __restrict__ gidx,
                              __half* __restrict__ xhi) {
    const int k = blockIdx.x;
    const int r = gidx[k];
    float4 v = reinterpret_cast<const float4*>(features + (size_t)r * F_DIM)[threadIdx.x];
    uint2 hv = make_uint2(pack_h2(__float2half(v.x), __float2half(v.y)),
                          pack_h2(__float2half(v.z), __float2half(v.w)));
    reinterpret_cast<uint2*>(xhi + (size_t)k * F_DIM)[threadIdx.x] = hv;
}

// ================= GEMM1: fp16 single-term, 6-stage pipeline =================
// C[4096,512] = (A16/2^15) @ Xhi. BM=BN=128, BK=64.
#define F_A_TILE 16384              // 128 rows x 128B (64 fp16)
#define F_B_TILE 16384              // 64 rows x 256B (128 fp16)
#define F_STAGE  (F_A_TILE + F_B_TILE)   // 32KB
#define F_NSTG   6
#define F_SMEM   (F_NSTG * F_STAGE)      // 192KB

__global__ __launch_bounds__(256, 1)
void gemm1_f16(const __half* __restrict__ A,
               const __half* __restrict__ Bhi,
               float* __restrict__ C) {
    constexpr int NCHUNK = S1_CNT / 64;
    constexpr int LDA = S1_CNT, LDB = F_DIM, LDC = 1024;
    extern __shared__ __align__(128) char smem[];
    const uint32_t sb = smem_u32(smem);
    const int tid = threadIdx.x;
    const int wid = tid >> 5;
    const int lane = tid & 31;
    const int bm = blockIdx.y * 128;
    const int bn = blockIdx.x * 128;
    const int wm = (wid & 3) * 32;
    const int wn = (wid >> 2) * 64;

    float acc[2][8][4];
#pragma unroll
    for (int m = 0; m < 2; ++m)
#pragma unroll
        for (int n = 0; n < 8; ++n)
#pragma unroll
            for (int j = 0; j < 4; ++j) acc[m][n][j] = 0.f;

#define F_LOAD(ch) do {                                                       \
    if ((ch) < NCHUNK) {                                                      \
        size_t k0 = (size_t)(ch) * 64;                                        \
        uint32_t sa = sb + (uint32_t)((ch) % F_NSTG) * F_STAGE;               \
        uint32_t sB = sa + F_A_TILE;                                          \
        _Pragma("unroll")                                                     \
        for (int i = 0; i < 4; ++i) {                                         \
            int lin = tid + i * 256;                                          \
            int row = lin >> 3, seg = lin & 7;                                \
            uint32_t d = sa + row * 128 + (((seg ^ (row & 7))) << 4);         \
            CP_ASYNC16(d, A + (size_t)(bm + row) * LDA + k0 + seg * 8);       \
        }                                                                     \
        _Pragma("unroll")                                                     \
        for (int i = 0; i < 4; ++i) {                                         \
            int lin = tid + i * 256;                                          \
            int row = lin >> 4, chk = lin & 15;                               \
            uint32_t d = sB + row * 256 + (((chk ^ (row & 7))) << 4);         \
            CP_ASYNC16(d, Bhi + (size_t)(k0 + row) * LDB + bn + chk * 8);     \
        }                                                                     \
    }                                                                         \
    CP_COMMIT();                                                              \
} while (0)

    F_LOAD(0); F_LOAD(1); F_LOAD(2); F_LOAD(3); F_LOAD(4);

    for (int ch = 0; ch < NCHUNK; ++ch) {
        CP_WAIT4();
        __syncthreads();
        F_LOAD(ch + 5);

        const uint32_t abase = sb + (uint32_t)(ch % F_NSTG) * F_STAGE;
        const uint32_t bbase = abase + F_A_TILE;
#pragma unroll
        for (int kk = 0; kk < 4; ++kk) {
            uint32_t ah[2][4];
#pragma unroll
            for (int m = 0; m < 2; ++m) {
                uint32_t r = wm + m * 16 + (lane & 15);
                uint32_t chunk = kk * 2 + (lane >> 4);
                ldsm_x4(ah[m], abase + r * 128 + ((chunk ^ (r & 7)) << 4));
            }
            uint32_t bh[4][4];
#pragma unroll
            for (int j = 0; j < 4; ++j) {
                uint32_t krow = kk * 16 + (lane & 15);
                uint32_t chk = (uint32_t)(wn >> 3) + j * 2 + (lane >> 4);
                ldsm_x4_t(bh[j], bbase + krow * 256 + ((chk ^ (krow & 7)) << 4));
            }
#pragma unroll
            for (int m = 0; m < 2; ++m)
#pragma unroll
                for (int j = 0; j < 4; ++j)
#pragma unroll
                    for (int h = 0; h < 2; ++h)
                        mma_f16(acc[m][j * 2 + h], ah[m], &bh[j][2 * h]);
        }
        __syncthreads();
    }

#pragma unroll
    for (int m = 0; m < 2; ++m) {
        const int row = bm + wm + m * 16 + (lane >> 2);
#pragma unroll
        for (int n8 = 0; n8 < 8; ++n8) {
            const int col = bn + wn + n8 * 8 + (lane & 3) * 2;
            *reinterpret_cast<float2*>(C + (size_t)row * LDC + col) =
                make_float2(acc[m][n8][0] * A_INV, acc[m][n8][1] * A_INV);
            *reinterpret_cast<float2*>(C + (size_t)(row + 8) * LDC + col) =
                make_float2(acc[m][n8][2] * A_INV, acc[m][n8][3] * A_INV);
        }
    }
#undef F_LOAD
}

// ================= bf16 3-term GEMM (cat1 @ w1), 3-stage =================
#define A_TILE_B 16384
#define B_TILE_B 16384
#define STAGE_B  (2 * A_TILE_B + 2 * B_TILE_B)
#define GSMEM    (3 * STAGE_B)

template<int KTOT, int LDA, int LDB, int LDC, bool RELU>
__global__ __launch_bounds__(256, 1)
void gemm_hmma3(const __nv_bfloat16* __restrict__ Ahi,
                const __nv_bfloat16* __restrict__ Alo,
                const __nv_bfloat16* __restrict__ Bhi,
                const __nv_bfloat16* __restrict__ Blo,
                float* __restrict__ C) {
    constexpr int NCHUNK = KTOT / 64;
    extern __shared__ __align__(128) char smem[];
    const uint32_t sb = smem_u32(smem);
    const int tid = threadIdx.x;
    const int wid = tid >> 5;
    const int lane = tid & 31;
    const int bm = blockIdx.y * 128;
    const int bn = blockIdx.x * 128;
    const int wm = (wid & 3) * 32;
    const int wn = (wid >> 2) * 64;

    float acc[2][8][4];
#pragma unroll
    for (int m = 0; m < 2; ++m)
#pragma unroll
        for (int n = 0; n < 8; ++n)
#pragma unroll
            for (int j = 0; j < 4; ++j) acc[m][n][j] = 0.f;

#define G_LOAD(ch, stg) do {                                                  \
    if ((ch) < NCHUNK) {                                                      \
        size_t k0 = (size_t)(ch) * 64;                                        \
        uint32_t sa = sb + (uint32_t)(stg) * STAGE_B;                         \
        uint32_t sB = sa + 2 * A_TILE_B;                                      \
        _Pragma("unroll")                                                     \
        for (int i = 0; i < 4; ++i) {                                         \
            int lin = tid + i * 256;                                          \
            int row = lin >> 3, seg = lin & 7;                                \
            uint32_t d = sa + row * 128 + (((seg ^ (row & 7))) << 4);         \
            CP_ASYNC16(d, Ahi + (size_t)(bm + row) * LDA + k0 + seg * 8);     \
            CP_ASYNC16(d + A_TILE_B, Alo + (size_t)(bm + row) * LDA + k0 + seg * 8); \
        }                                                                     \
        _Pragma("unroll")                                                     \
        for (int i = 0; i < 4; ++i) {                                         \
            int lin = tid + i * 256;                                          \
            int row = lin >> 4, chk = lin & 15;                               \
            uint32_t d = sB + row * 256 + (((chk ^ (row & 7))) << 4);         \
            CP_ASYNC16(d, Bhi + (size_t)(k0 + row) * LDB + bn + chk * 8);     \
            CP_ASYNC16(d + B_TILE_B, Blo + (size_t)(k0 + row) * LDB + bn + chk * 8); \
        }                                                                     \
    }                                                                         \
    CP_COMMIT();                                                              \
} while (0)

    G_LOAD(0, 0);
    G_LOAD(1, 1);

    int stg = 0;
    for (int ch = 0; ch < NCHUNK; ++ch) {
        CP_WAIT1();
        __syncthreads();
        G_LOAD(ch + 2, (stg + 2 >= 3) ? (stg - 1) : (stg + 2));

        const uint32_t abase = sb + (uint32_t)stg * STAGE_B;
        const uint32_t bbase = abase + 2 * A_TILE_B;
#pragma unroll
        for (int kk = 0; kk < 4; ++kk) {
            uint32_t ah[2][4], al[2][4];
#pragma unroll
            for (int m = 0; m < 2; ++m) {
                uint32_t r = wm + m * 16 + (lane & 15);
                uint32_t chunk = kk * 2 + (lane >> 4);
                uint32_t ad = abase + r * 128 + ((chunk ^ (r & 7)) << 4);
                ldsm_x4(ah[m], ad);
                ldsm_x4(al[m], ad + A_TILE_B);
            }
            uint32_t bh[4][4], bl[4][4];
#pragma unroll
            for (int j = 0; j < 4; ++j) {
                uint32_t krow = kk * 16 + (lane & 15);
                uint32_t chk = (uint32_t)(wn >> 3) + j * 2 + (lane >> 4);
                uint32_t bd = bbase + krow * 256 + ((chk ^ (krow & 7)) << 4);
                ldsm_x4_t(bh[j], bd);
                ldsm_x4_t(bl[j], bd + B_TILE_B);
            }
#pragma unroll
            for (int m = 0; m < 2; ++m)
#pragma unroll
                for (int j = 0; j < 4; ++j)
#pragma unroll
                    for (int h = 0; h < 2; ++h) {
                        const int n8 = j * 2 + h;
                        mma_bf16(acc[m][n8], ah[m], &bh[j][2 * h]);
                        mma_bf16(acc[m][n8], ah[m], &bl[j][2 * h]);
                        mma_bf16(acc[m][n8], al[m], &bh[j][2 * h]);
                    }
        }
        stg = (stg + 1 == 3) ? 0 : stg + 1;
    }

#pragma unroll
    for (int m = 0; m < 2; ++m) {
        const int row = bm + wm + m * 16 + (lane >> 2);
#pragma unroll
        for (int n8 = 0; n8 < 8; ++n8) {
            const int col = bn + wn + n8 * 8 + (lane & 3) * 2;
            float2 v0 = make_float2(acc[m][n8][0], acc[m][n8][1]);
            float2 v1 = make_float2(acc[m][n8][2], acc[m][n8][3]);
            if (RELU) {
                v0.x = fmaxf(v0.x, 0.f); v0.y = fmaxf(v0.y, 0.f);
                v1.x = fmaxf(v1.x, 0.f); v1.y = fmaxf(v1.y, 0.f);
            }
            *reinterpret_cast<float2*>(C + (size_t)row * LDC + col) = v0;
            *reinterpret_cast<float2*>(C + (size_t)(row + 8) * LDC + col) = v1;
        }
    }
#undef G_LOAD
}

// ================= f32x2 SGEMM (layer-2 small GEMMs) =================
template<int BMt, int BNt, int BKt, int TM, int TN, bool GATHER_B, bool RELU>
__global__ __launch_bounds__((BMt / TM) * (BNt / TN))
void sgemm_kernel(int M, int N, int K,
                  const float* __restrict__ Am, int lda,
                  const float* __restrict__ Bm, int ldb,
                  const int* __restrict__ bidx,
                  float* __restrict__ Cm, int ldc) {
    constexpr int THREADS = (BMt / TM) * (BNt / TN);
    __shared__ __align__(16) float As[BKt][BMt];
    __shared__ __align__(16) float Bs[BKt][BNt];

    const int tid = threadIdx.x;
    const int block_m = blockIdx.y * BMt;
    const int block_n = blockIdx.x * BNt;
    const int tn = (tid % (BNt / TN)) * TN;
    const int tm = (tid / (BNt / TN)) * TM;

    u64t acc2[TM][TN / 2];
#pragma unroll
    for (int i = 0; i < TM; ++i)
#pragma unroll
        for (int j = 0; j < TN / 2; ++j) acc2[i][j] = 0ull;

    constexpr int LA = (BMt * BKt) / (4 * THREADS);
    constexpr int LB = (BKt * BNt) / (4 * THREADS);
    constexpr int A_F4_PER_ROW = BKt / 4;
    constexpr int B_F4_PER_ROW = BNt / 4;

    for (int k0 = 0; k0 < K; k0 += BKt) {
#pragma unroll
        for (int i = 0; i < LA; ++i) {
            int idx = tid + i * THREADS;
            int row = idx / A_F4_PER_ROW;
            int c4  = idx % A_F4_PER_ROW;
            float4 v = *reinterpret_cast<const float4*>(
                Am + (size_t)(block_m + row) * lda + k0 + c4 * 4);
            As[c4 * 4 + 0][row] = v.x;
            As[c4 * 4 + 1][row] = v.y;
            As[c4 * 4 + 2][row] = v.z;
            As[c4 * 4 + 3][row] = v.w;
        }
#pragma unroll
        for (int i = 0; i < LB; ++i) {
            int idx = tid + i * THREADS;
            int row = idx / B_F4_PER_ROW;
            int c4  = idx % B_F4_PER_ROW;
            const float* brow;
            if (GATHER_B) brow = Bm + (size_t)bidx[k0 + row] * ldb;
            else          brow = Bm + (size_t)(k0 + row) * ldb;
            float4 v = *reinterpret_cast<const float4*>(brow + block_n + c4 * 4);
            *reinterpret_cast<float4*>(&Bs[row][c4 * 4]) = v;
        }
        __syncthreads();
#pragma unroll
        for (int kk = 0; kk < BKt; ++kk) {
            u64t b2[TN / 2];
            const u64t* bs2 = reinterpret_cast<const u64t*>(&Bs[kk][tn]);
#pragma unroll
            for (int j = 0; j < TN / 2; ++j) b2[j] = bs2[j];
#pragma unroll
            for (int i = 0; i < TM; ++i) {
                u64t a2 = pack_dup(As[kk][tm + i]);
#pragma unroll
                for (int j = 0; j < TN / 2; ++j) fma2(acc2[i][j], a2, b2[j]);
            }
        }
        __syncthreads();
    }
#pragma unroll
    for (int i = 0; i < TM; ++i) {
        float* crow = Cm + (size_t)(block_m + tm + i) * ldc + block_n + tn;
#pragma unroll
        for (int j = 0; j < TN / 2; j += 2) {
            float2 v0 = unpack2(acc2[i][j]);
            float2 v1 = unpack2(acc2[i][j + 1]);
            float4 o;
            if (RELU) {
                o.x = fmaxf(v0.x, 0.f); o.y = fmaxf(v0.y, 0.f);
                o.z = fmaxf(v1.x, 0.f); o.w = fmaxf(v1.y, 0.f);
            } else {
                o.x = v0.x; o.y = v0.y; o.z = v1.x; o.w = v1.y;
            }
            *reinterpret_cast<float4*>(crow + j * 2) = o;
        }
    }
}

// ================= classifier + softmax =================
__global__ void cls_softmax_kernel(const float* __restrict__ h2,
                                   const float* __restrict__ wc,
                                   float* __restrict__ out) {
    __shared__ float sh[D_DIM];
    __shared__ float red[C_DIM];
    const int b = blockIdx.x;
    const int c = threadIdx.x;
    for (int i = c; i < D_DIM; i += C_DIM) sh[i] = h2[(size_t)b * D_DIM + i];
    __syncthreads();
    float acc = 0.f;
#pragma unroll 8
    for (int k = 0; k < D_DIM; ++k)
        acc = fmaf(sh[k], wc[(size_t)k * C_DIM + c], acc);
    red[c] = acc;
    __syncthreads();
    for (int s = C_DIM / 2; s > 0; s >>= 1) {
        if (c < s) red[c] = fmaxf(red[c], red[c + s]);
        __syncthreads();
    }
    float mx = red[0];
    __syncthreads();
    float e = expf(acc - mx);
    red[c] = e;
    __syncthreads();
    for (int s = C_DIM / 2; s > 0; s >>= 1) {
        if (c < s) red[c] += red[c + s];
        __syncthreads();
    }
    out[(size_t)b * C_DIM + c] = e / red[0];
}

// ================= launch =================
extern "C" void kernel_launch(void* const* d_in, const int* in_sizes, int n_in,
                              void* d_out, int out_size) {
    const float* features  = (const float*)d_in[0];
    const int*   src_nodes = (const int*)d_in[1];
    const int*   dst_idx1  = (const int*)d_in[2];
    const int*   src_idx1  = (const int*)d_in[3];
    const float* dif_mat1  = (const float*)d_in[4];
    const int*   dst_idx2  = (const int*)d_in[5];
    const int*   src_idx2  = (const int*)d_in[6];
    const float* dif_mat2  = (const float*)d_in[7];
    const float* w1        = (const float*)d_in[8];
    const float* w2        = (const float*)d_in[9];
    const float* w_cls     = (const float*)d_in[10];
    float* out = (float*)d_out;

    float *cat1, *h1, *cat2, *h2;
    int* gidx1;
    __half *a16, *xhi;
    __nv_bfloat16 *c1hi, *c1lo, *w1hi, *w1lo;
    cudaGetSymbolAddress((void**)&cat1,  g_cat1);
    cudaGetSymbolAddress((void**)&h1,    g_h1);
    cudaGetSymbolAddress((void**)&cat2,  g_cat2);
    cudaGetSymbolAddress((void**)&h2,    g_h2);
    cudaGetSymbolAddress((void**)&gidx1, g_gidx1);
    cudaGetSymbolAddress((void**)&a16,   g_a16);
    cudaGetSymbolAddress((void**)&xhi,   g_xhi);
    cudaGetSymbolAddress((void**)&c1hi,  g_c1hi);
    cudaGetSymbolAddress((void**)&c1lo,  g_c1lo);
    cudaGetSymbolAddress((void**)&w1hi,  g_w1hi);
    cudaGetSymbolAddress((void**)&w1lo,  g_w1lo);

    cudaFuncSetAttribute((const void*)gemm1_f16,
                         cudaFuncAttributeMaxDynamicSharedMemorySize, F_SMEM);
    cudaFuncSetAttribute((const void*)gemm_hmma3<1024, 1024, D_DIM, D_DIM, true>,
                         cudaFuncAttributeMaxDynamicSharedMemorySize, GSMEM);

    // 0) index composition, dst gather, operand prep
    build_gidx_kernel<<<(S1_CNT + 255) / 256, 256>>>(src_nodes, src_idx1, gidx1, S1_CNT);
    gather_cat_kernel<<<B1_CNT, 128>>>(features, dst_idx1, src_nodes, cat1);
    prep_x_kernel<<<S1_CNT, 128>>>(features, gidx1, xhi);
    {   // scaled fp16 A
        int n8 = (B1_CNT * S1_CNT) / 8;
        scale_f16_kernel<<<n8 / 256, 256>>>(dif_mat1, a16, n8);
    }

    // 1) agg1 = dif_mat1 @ X -> cat1[:, 0:512]   (fp16 single-term)
    gemm1_f16<<<dim3(F_DIM / 128, B1_CNT / 128), 256, F_SMEM>>>(a16, xhi, cat1);

    // 2) split cat1 / w1 (bf16), h1 = relu(cat1 @ w1)  (bf16 3-term)
    {
        int n8 = (B1_CNT * 1024) / 8;
        split_kernel<<<n8 / 256, 256>>>(cat1, c1hi, c1lo, n8);
        int m8 = (1024 * D_DIM) / 8;
        split_kernel<<<m8 / 256, 256>>>(w1, w1hi, w1lo, m8);
    }
    gemm_hmma3<1024, 1024, D_DIM, D_DIM, true>
        <<<dim3(D_DIM / 128, B1_CNT / 128), 256, GSMEM>>>(c1hi, c1lo, w1hi, w1lo, h1);

    // 3) layer 2 (small)
    gather_cat_kernel<<<B2_CNT, 128>>>(h1, dst_idx2, nullptr, cat2);
    sgemm_kernel<64, 64, 16, 4, 4, true, false>
        <<<dim3(D_DIM / 64, B2_CNT / 64), 256>>>(
            B2_CNT, D_DIM, S2_CNT, dif_mat2, S2_CNT, h1, D_DIM, src_idx2, cat2, 1024);
    sgemm_kernel<64, 64, 16, 4, 4, false, true>
        <<<dim3(D_DIM / 64, B2_CNT / 64), 256>>>(
            B2_CNT, D_DIM, 2 * D_DIM, cat2, 1024, w2, D_DIM, nullptr, h2, D_DIM);

    // 4) out = softmax(h2 @ w_cls)
    cls_softmax_kernel<<<B2_CNT, C_DIM>>>(h2, w_cls, out);
}

// round 7
// speedup vs baseline: 6.8364x; 1.2697x over previous
#include <cuda_runtime.h>
#include <cuda_bf16.h>
#include <cuda_fp16.h>
#include <cstdint>
#include <math.h>

// ---------------- problem constants ----------------
#define V_NODES 100000
#define F_DIM   512
#define D_DIM   512
#define C_DIM   128
#define N1_CNT  36864
#define S1_CNT  32768
#define B1_CNT  4096
#define S2_CNT  3584
#define B2_CNT  512

#define A_SCALE 32768.0f
#define A_INV   (1.0f / 32768.0f)

// ---------------- scratch (device globals; no allocation allowed) ----------------
__device__ float g_cat1[B1_CNT * 1024];
__device__ float g_h1  [B1_CNT * D_DIM];
__device__ float g_cat2[B2_CNT * 1024];
__device__ float g_h2  [B2_CNT * D_DIM];
__device__ int   g_gidx1[S1_CNT];
__device__ uint8_t g_a8 [(size_t)B1_CNT * S1_CNT];        // dif_mat1*2^15 e4m3 [4096,32768]
__device__ uint8_t g_xt8[(size_t)F_DIM * S1_CNT];         // X^T e4m3 [512,32768] (n-major)
__device__ __half  g_a2 [(size_t)B2_CNT * S2_CNT];        // dif_mat2*2^15 fp16 [512,3584]
__device__ __half  g_h1f16[(size_t)B1_CNT * D_DIM];       // h1 fp16 [4096,512]
__device__ __nv_bfloat16 g_c1hi[(size_t)B1_CNT * 1024];
__device__ __nv_bfloat16 g_c1lo[(size_t)B1_CNT * 1024];
__device__ __nv_bfloat16 g_w1hi[1024 * D_DIM];
__device__ __nv_bfloat16 g_w1lo[1024 * D_DIM];
__device__ __nv_bfloat16 g_c2hi[(size_t)B2_CNT * 1024];
__device__ __nv_bfloat16 g_c2lo[(size_t)B2_CNT * 1024];
__device__ __nv_bfloat16 g_w2hi[1024 * D_DIM];
__device__ __nv_bfloat16 g_w2lo[1024 * D_DIM];

typedef unsigned long long u64t;

// ================= baseline-PTX helpers (compute_103-safe) =================
__device__ __forceinline__ uint32_t smem_u32(const void* p) {
    uint32_t a;
    asm("{ .reg .u64 t; cvta.to.shared.u64 t, %1; cvt.u32.u64 %0, t; }" : "=r"(a) : "l"(p));
    return a;
}
#define CP_ASYNC16(sm, gm) asm volatile("cp.async.cg.shared.global [%0], [%1], 16;" :: "r"(sm), "l"(gm) : "memory")
#define CP_COMMIT()        asm volatile("cp.async.commit_group;" ::: "memory")
#define CP_WAIT1()         asm volatile("cp.async.wait_group 1;" ::: "memory")
#define CP_WAIT4()         asm volatile("cp.async.wait_group 4;" ::: "memory")

__device__ __forceinline__ void ldsm_x4(uint32_t* r, uint32_t addr) {
    asm volatile("ldmatrix.sync.aligned.m8n8.x4.shared.b16 {%0,%1,%2,%3}, [%4];"
        : "=r"(r[0]), "=r"(r[1]), "=r"(r[2]), "=r"(r[3]) : "r"(addr));
}
__device__ __forceinline__ void ldsm_x4_t(uint32_t* r, uint32_t addr) {
    asm volatile("ldmatrix.sync.aligned.m8n8.x4.trans.shared.b16 {%0,%1,%2,%3}, [%4];"
        : "=r"(r[0]), "=r"(r[1]), "=r"(r[2]), "=r"(r[3]) : "r"(addr));
}
__device__ __forceinline__ void mma_bf16(float* d, const uint32_t* a, const uint32_t* b) {
    asm volatile("mma.sync.aligned.m16n8k16.row.col.f32.bf16.bf16.f32 "
        "{%0,%1,%2,%3}, {%4,%5,%6,%7}, {%8,%9}, {%0,%1,%2,%3};"
        : "+f"(d[0]), "+f"(d[1]), "+f"(d[2]), "+f"(d[3])
        : "r"(a[0]), "r"(a[1]), "r"(a[2]), "r"(a[3]), "r"(b[0]), "r"(b[1]));
}
__device__ __forceinline__ void mma_f16(float* d, const uint32_t* a, const uint32_t* b) {
    asm volatile("mma.sync.aligned.m16n8k16.row.col.f32.f16.f16.f32 "
        "{%0,%1,%2,%3}, {%4,%5,%6,%7}, {%8,%9}, {%0,%1,%2,%3};"
        : "+f"(d[0]), "+f"(d[1]), "+f"(d[2]), "+f"(d[3])
        : "r"(a[0]), "r"(a[1]), "r"(a[2]), "r"(a[3]), "r"(b[0]), "r"(b[1]));
}
__device__ __forceinline__ void mma_fp8(float* d, const uint32_t* a, const uint32_t* b) {
    asm volatile("mma.sync.aligned.m16n8k32.row.col.f32.e4m3.e4m3.f32 "
        "{%0,%1,%2,%3}, {%4,%5,%6,%7}, {%8,%9}, {%0,%1,%2,%3};"
        : "+f"(d[0]), "+f"(d[1]), "+f"(d[2]), "+f"(d[3])
        : "r"(a[0]), "r"(a[1]), "r"(a[2]), "r"(a[3]), "r"(b[0]), "r"(b[1]));
}
__device__ __forceinline__ uint32_t pack_bf2(__nv_bfloat16 a, __nv_bfloat16 b) {
    __nv_bfloat162 t = __halves2bfloat162(a, b);
    return *reinterpret_cast<uint32_t*>(&t);
}
__device__ __forceinline__ uint32_t pack_h2(__half a, __half b) {
    __half2 t = __halves2half2(a, b);
    return *reinterpret_cast<uint32_t*>(&t);
}
__device__ __forceinline__ void split_bf(float f, __nv_bfloat16& hi, __nv_bfloat16& lo) {
    hi = __float2bfloat16(f);
    lo = __float2bfloat16(f - __bfloat162float(hi));
}
// pack 4 floats -> 4 e4m3 bytes (f0 in lowest byte)
__device__ __forceinline__ uint32_t pack_e4m3_4(float f0, float f1, float f2, float f3) {
    uint16_t lo, hi;
    asm("cvt.rn.satfinite.e4m3x2.f32 %0, %1, %2;" : "=h"(lo) : "f"(f1), "f"(f0));
    asm("cvt.rn.satfinite.e4m3x2.f32 %0, %1, %2;" : "=h"(hi) : "f"(f3), "f"(f2));
    return (uint32_t)lo | ((uint32_t)hi << 16);
}

// ================= small kernels =================
__global__ void build_gidx_kernel(const int* __restrict__ src_nodes,
                                  const int* __restrict__ src_idx1,
                                  int* __restrict__ out, int n) {
    int k = blockIdx.x * blockDim.x + threadIdx.x;
    if (k < n) out[k] = src_nodes[src_idx1[k]];
}

__global__ void gather_cat_kernel(const float* __restrict__ src,
                                  const int* __restrict__ idx,
                                  const int* __restrict__ map,
                                  float* __restrict__ cat) {
    int b = blockIdx.x;
    int r = idx[b];
    if (map) r = map[r];
    const float4* s = reinterpret_cast<const float4*>(src + (size_t)r * 512);
    float4* d = reinterpret_cast<float4*>(cat + (size_t)b * 1024 + 512);
    d[threadIdx.x] = s[threadIdx.x];
}

// fp32 -> bf16 hi/lo split (8 elems / thread)
__global__ void split_kernel(const float* __restrict__ src,
                             __nv_bfloat16* __restrict__ hi,
                             __nv_bfloat16* __restrict__ lo, int n8) {
    int i = blockIdx.x * blockDim.x + threadIdx.x;
    if (i >= n8) return;
    const float4* s = reinterpret_cast<const float4*>(src) + 2 * (size_t)i;
    float4 a = s[0], b = s[1];
    float f[8] = {a.x, a.y, a.z, a.w, b.x, b.y, b.z, b.w};
    __nv_bfloat16 h[8], l[8];
#pragma unroll
    for (int q = 0; q < 8; ++q) split_bf(f[q], h[q], l[q]);
    uint4 hv = make_uint4(pack_bf2(h[0], h[1]), pack_bf2(h[2], h[3]),
                          pack_bf2(h[4], h[5]), pack_bf2(h[6], h[7]));
    uint4 lv = make_uint4(pack_bf2(l[0], l[1]), pack_bf2(l[2], l[3]),
                          pack_bf2(l[4], l[5]), pack_bf2(l[6], l[7]));
    reinterpret_cast<uint4*>(hi)[i] = hv;
    reinterpret_cast<uint4*>(lo)[i] = lv;
}

// fp32 * 2^15 -> e4m3 (8 elems / thread)
__global__ void scale_a8_kernel(const float* __restrict__ src,
                                uint8_t* __restrict__ dst, int n8) {
    int i = blockIdx.x * blockDim.x + threadIdx.x;
    if (i >= n8) return;
    const float4* s = reinterpret_cast<const float4*>(src) + 2 * (size_t)i;
    float4 a = s[0], b = s[1];
    uint32_t p0 = pack_e4m3_4(a.x * A_SCALE, a.y * A_SCALE, a.z * A_SCALE, a.w * A_SCALE);
    uint32_t p1 = pack_e4m3_4(b.x * A_SCALE, b.y * A_SCALE, b.z * A_SCALE, b.w * A_SCALE);
    reinterpret_cast<uint2*>(dst)[i] = make_uint2(p0, p1);
}

// fp32 * 2^15 -> fp16 (8 elems / thread)
__global__ void scale_f16_kernel(const float* __restrict__ src,
                                 __half* __restrict__ dst, int n8) {
    int i = blockIdx.x * blockDim.x + threadIdx.x;
    if (i >= n8) return;
    const float4* s = reinterpret_cast<const float4*>(src) + 2 * (size_t)i;
    float4 a = s[0], b = s[1];
    float f[8] = {a.x, a.y, a.z, a.w, b.x, b.y, b.z, b.w};
    __half h[8];
#pragma unroll
    for (int q = 0; q < 8; ++q) h[q] = __float2half(f[q] * A_SCALE);
    uint4 v = make_uint4(pack_h2(h[0], h[1]), pack_h2(h[2], h[3]),
                         pack_h2(h[4], h[5]), pack_h2(h[6], h[7]));
    reinterpret_cast<uint4*>(dst)[i] = v;
}

// fp32 -> fp16 (4 elems / thread)
__global__ void f32_to_f16_kernel(const float* __restrict__ src,
                                  __half* __restrict__ dst, int n4) {
    int i = blockIdx.x * blockDim.x + threadIdx.x;
    if (i >= n4) return;
    float4 v = reinterpret_cast<const float4*>(src)[i];
    uint2 o = make_uint2(pack_h2(__float2half(v.x), __float2half(v.y)),
                         pack_h2(__float2half(v.z), __float2half(v.w)));
    reinterpret_cast<uint2*>(dst)[i] = o;
}

// gather + transpose + e4m3: XT[n][k] = e4m3(features[gidx[k]][n])
__global__ void prep_xt8_kernel(const float* __restrict__ features,
                                const int* __restrict__ gidx,
                                uint8_t* __restrict__ xt) {
    __shared__ float tile[128][65];
    const int k0 = blockIdx.x * 128;
    const int n0 = blockIdx.y * 64;
    const int tid = threadIdx.x;  // 128
    for (int i = tid; i < 128 * 16; i += 128) {
        int r = i >> 4, c4 = i & 15;
        float4 v = *reinterpret_cast<const float4*>(
            features + (size_t)gidx[k0 + r] * F_DIM + n0 + c4 * 4);
        tile[r][c4 * 4 + 0] = v.x; tile[r][c4 * 4 + 1] = v.y;
        tile[r][c4 * 4 + 2] = v.z; tile[r][c4 * 4 + 3] = v.w;
    }
    __syncthreads();
    for (int i = tid; i < 64 * 32; i += 128) {
        int n = i >> 5, kg = i & 31;
        uint32_t p = pack_e4m3_4(tile[kg * 4 + 0][n], tile[kg * 4 + 1][n],
                                 tile[kg * 4 + 2][n], tile[kg * 4 + 3][n]);
        *reinterpret_cast<uint32_t*>(xt + (size_t)(n0 + n) * S1_CNT + k0 + kg * 4) = p;
    }
}

// ================= GEMM1: e4m3 fp8, BK=128, 6-stage pipeline =================
// C[4096,512] = (A8/2^15) @ X, with X stored transposed [n][k].
#define P_A_TILE 16384              // 128 rows x 128B (128 fp8)
#define P_B_TILE 16384              // 128 n-rows x 128B
#define P_STAGE  (P_A_TILE + P_B_TILE)   // 32KB
#define P_NSTG   6
#define P_SMEM   (P_NSTG * P_STAGE)      // 192KB

__global__ __launch_bounds__(256, 1)
void gemm1_fp8(const uint8_t* __restrict__ A,
               const uint8_t* __restrict__ Bt,
               float* __restrict__ C) {
    constexpr int NCHUNK = S1_CNT / 128;   // 256
    constexpr int LDC = 1024;
    extern __shared__ __align__(128) char smem[];
    const uint32_t sb = smem_u32(smem);
    const int tid = threadIdx.x;
    const int wid = tid >> 5;
    const int lane = tid & 31;
    const int bm = blockIdx.y * 128;
    const int bn = blockIdx.x * 128;
    const int wm = (wid & 3) * 32;
    const int wn = (wid >> 2) * 64;

    float acc[2][8][4];
#pragma unroll
    for (int m = 0; m < 2; ++m)
#pragma unroll
        for (int n = 0; n < 8; ++n)
#pragma unroll
            for (int j = 0; j < 4; ++j) acc[m][n][j] = 0.f;

#define P_LOAD(ch) do {                                                       \
    if ((ch) < NCHUNK) {                                                      \
        size_t k0 = (size_t)(ch) * 128;                                       \
        uint32_t sa = sb + (uint32_t)((ch) % P_NSTG) * P_STAGE;               \
        uint32_t sB = sa + P_A_TILE;                                          \
        _Pragma("unroll")                                                     \
        for (int i = 0; i < 4; ++i) {                                         \
            int lin = tid + i * 256;                                          \
            int row = lin >> 3, seg = lin & 7;                                \
            uint32_t off = row * 128 + (((seg ^ (row & 7))) << 4);            \
            CP_ASYNC16(sa + off, A  + (size_t)(bm + row) * S1_CNT + k0 + seg * 16); \
            CP_ASYNC16(sB + off, Bt + (size_t)(bn + row) * S1_CNT + k0 + seg * 16); \
        }                                                                     \
    }                                                                         \
    CP_COMMIT();                                                              \
} while (0)

    P_LOAD(0); P_LOAD(1); P_LOAD(2); P_LOAD(3); P_LOAD(4);

    for (int ch = 0; ch < NCHUNK; ++ch) {
        CP_WAIT4();
        __syncthreads();
        P_LOAD(ch + 5);

        const uint32_t abase = sb + (uint32_t)(ch % P_NSTG) * P_STAGE;
        const uint32_t bbase = abase + P_A_TILE;
#pragma unroll
        for (int kk = 0; kk < 4; ++kk) {   // k-steps of 32 fp8
            uint32_t ar[2][4];
#pragma unroll
            for (int m = 0; m < 2; ++m) {
                uint32_t r = wm + m * 16 + (lane & 15);
                uint32_t c = kk * 2 + (lane >> 4);
                ldsm_x4(ar[m], abase + r * 128 + ((c ^ (r & 7)) << 4));
            }
            uint32_t br[4][4];
#pragma unroll
            for (int j = 0; j < 4; ++j) {
                uint32_t nrow = wn + j * 16 + (lane & 7) + ((lane & 16) >> 1);
                uint32_t c = kk * 2 + ((lane >> 3) & 1);
                ldsm_x4(br[j], bbase + nrow * 128 + ((c ^ (nrow & 7)) << 4));
            }
#pragma unroll
            for (int m = 0; m < 2; ++m)
#pragma unroll
                for (int j = 0; j < 4; ++j)
#pragma unroll
                    for (int h = 0; h < 2; ++h)
                        mma_fp8(acc[m][j * 2 + h], ar[m], &br[j][2 * h]);
        }
        __syncthreads();
    }

#pragma unroll
    for (int m = 0; m < 2; ++m) {
        const int row = bm + wm + m * 16 + (lane >> 2);
#pragma unroll
        for (int n8 = 0; n8 < 8; ++n8) {
            const int col = bn + wn + n8 * 8 + (lane & 3) * 2;
            *reinterpret_cast<float2*>(C + (size_t)row * LDC + col) =
                make_float2(acc[m][n8][0] * A_INV, acc[m][n8][1] * A_INV);
            *reinterpret_cast<float2*>(C + (size_t)(row + 8) * LDC + col) =
                make_float2(acc[m][n8][2] * A_INV, acc[m][n8][3] * A_INV);
        }
    }
#undef P_LOAD
}

// ================= GEMM2 (agg2): fp16 single-term, gathered B =================
// C[512,512] (cat2 cols 0:512) = (A2/2^15) @ h1f16[src_idx2]. BK=64, 6 stages.
#define Q_A_TILE 16384
#define Q_B_TILE 16384
#define Q_STAGE  (Q_A_TILE + Q_B_TILE)
#define Q_NSTG   6
#define Q_SMEM   (Q_NSTG * Q_STAGE)

__global__ __launch_bounds__(256, 1)
void gemm2_f16(const __half* __restrict__ A,
               const __half* __restrict__ B,
               const int* __restrict__ gidx,
               float* __restrict__ C) {
    constexpr int NCHUNK = S2_CNT / 64;    // 56
    constexpr int LDA = S2_CNT, LDB = D_DIM, LDC = 1024;
    extern __shared__ __align__(128) char smem[];
    const uint32_t sb = smem_u32(smem);
    const int tid = threadIdx.x;
    const int wid = tid >> 5;
    const int lane = tid & 31;
    const int bm = blockIdx.y * 128;
    const int bn = blockIdx.x * 128;
    const int wm = (wid & 3) * 32;
    const int wn = (wid >> 2) * 64;

    float acc[2][8][4];
#pragma unroll
    for (int m = 0; m < 2; ++m)
#pragma unroll
        for (int n = 0; n < 8; ++n)
#pragma unroll
            for (int j = 0; j < 4; ++j) acc[m][n][j] = 0.f;

#define Q_LOAD(ch) do {                                                       \
    if ((ch) < NCHUNK) {                                                      \
        size_t k0 = (size_t)(ch) * 64;                                        \
        uint32_t sa = sb + (uint32_t)((ch) % Q_NSTG) * Q_STAGE;               \
        uint32_t sB = sa + Q_A_TILE;                                          \
        _Pragma("unroll")                                                     \
        for (int i = 0; i < 4; ++i) {                                         \
            int lin = tid + i * 256;                                          \
            int row = lin >> 3, seg = lin & 7;                                \
            uint32_t d = sa + row * 128 + (((seg ^ (row & 7))) << 4);         \
            CP_ASYNC16(d, A + (size_t)(bm + row) * LDA + k0 + seg * 8);       \
        }                                                                     \
        _Pragma("unroll")                                                     \
        for (int i = 0; i < 4; ++i) {                                         \
            int lin = tid + i * 256;                                          \
            int row = lin >> 4, chk = lin & 15;                               \
            int g = gidx[k0 + row];                                           \
            uint32_t d = sB + row * 256 + (((chk ^ (row & 7))) << 4);         \
            CP_ASYNC16(d, B + (size_t)g * LDB + bn + chk * 8);                \
        }                                                                     \
    }                                                                         \
    CP_COMMIT();                                                              \
} while (0)

    Q_LOAD(0); Q_LOAD(1); Q_LOAD(2); Q_LOAD(3); Q_LOAD(4);

    for (int ch = 0; ch < NCHUNK; ++ch) {
        CP_WAIT4();
        __syncthreads();
        Q_LOAD(ch + 5);

        const uint32_t abase = sb + (uint32_t)(ch % Q_NSTG) * Q_STAGE;
        const uint32_t bbase = abase + Q_A_TILE;
#pragma unroll
        for (int kk = 0; kk < 4; ++kk) {
            uint32_t ah[2][4];
#pragma unroll
            for (int m = 0; m < 2; ++m) {
                uint32_t r = wm + m * 16 + (lane & 15);
                uint32_t c = kk * 2 + (lane >> 4);
                ldsm_x4(ah[m], abase + r * 128 + ((c ^ (r & 7)) << 4));
            }
            uint32_t bh[4][4];
#pragma unroll
            for (int j = 0; j < 4; ++j) {
                uint32_t krow = kk * 16 + (lane & 15);
                uint32_t chk = (uint32_t)(wn >> 3) + j * 2 + (lane >> 4);
                ldsm_x4_t(bh[j], bbase + krow * 256 + ((chk ^ (krow & 7)) << 4));
            }
#pragma unroll
            for (int m = 0; m < 2; ++m)
#pragma unroll
                for (int j = 0; j < 4; ++j)
#pragma unroll
                    for (int h = 0; h < 2; ++h)
                        mma_f16(acc[m][j * 2 + h], ah[m], &bh[j][2 * h]);
        }
        __syncthreads();
    }

#pragma unroll
    for (int m = 0; m < 2; ++m) {
        const int row = bm + wm + m * 16 + (lane >> 2);
#pragma unroll
        for (int n8 = 0; n8 < 8; ++n8) {
            const int col = bn + wn + n8 * 8 + (lane & 3) * 2;
            *reinterpret_cast<float2*>(C + (size_t)row * LDC + col) =
                make_float2(acc[m][n8][0] * A_INV, acc[m][n8][1] * A_INV);
            *reinterpret_cast<float2*>(C + (size_t)(row + 8) * LDC + col) =
                make_float2(acc[m][n8][2] * A_INV, acc[m][n8][3] * A_INV);
        }
    }
#undef Q_LOAD
}

// ================= bf16 3-term GEMM (cat @ w), 3-stage =================
#define A_TILE_B 16384
#define B_TILE_B 16384
#define STAGE_B  (2 * A_TILE_B + 2 * B_TILE_B)
#define GSMEM    (3 * STAGE_B)

template<int KTOT, int LDA, int LDB, int LDC, bool RELU>
__global__ __launch_bounds__(256, 1)
void gemm_hmma3(const __nv_bfloat16* __restrict__ Ahi,
                const __nv_bfloat16* __restrict__ Alo,
                const __nv_bfloat16* __restrict__ Bhi,
                const __nv_bfloat16* __restrict__ Blo,
                float* __restrict__ C) {
    constexpr int NCHUNK = KTOT / 64;
    extern __shared__ __align__(128) char smem[];
    const uint32_t sb = smem_u32(smem);
    const int tid = threadIdx.x;
    const int wid = tid >> 5;
    const int lane = tid & 31;
    const int bm = blockIdx.y * 128;
    const int bn = blockIdx.x * 128;
    const int wm = (wid & 3) * 32;
    const int wn = (wid >> 2) * 64;

    float acc[2][8][4];
#pragma unroll
    for (int m = 0; m < 2; ++m)
#pragma unroll
        for (int n = 0; n < 8; ++n)
#pragma unroll
            for (int j = 0; j < 4; ++j) acc[m][n][j] = 0.f;

#define G_LOAD(ch, stg) do {                                                  \
    if ((ch) < NCHUNK) {                                                      \
        size_t k0 = (size_t)(ch) * 64;                                        \
        uint32_t sa = sb + (uint32_t)(stg) * STAGE_B;                         \
        uint32_t sB = sa + 2 * A_TILE_B;                                      \
        _Pragma("unroll")                                                     \
        for (int i = 0; i < 4; ++i) {                                         \
            int lin = tid + i * 256;                                          \
            int row = lin >> 3, seg = lin & 7;                                \
            uint32_t d = sa + row * 128 + (((seg ^ (row & 7))) << 4);         \
            CP_ASYNC16(d, Ahi + (size_t)(bm + row) * LDA + k0 + seg * 8);     \
            CP_ASYNC16(d + A_TILE_B, Alo + (size_t)(bm + row) * LDA + k0 + seg * 8); \
        }                                                                     \
        _Pragma("unroll")                                                     \
        for (int i = 0; i < 4; ++i) {                                         \
            int lin = tid + i * 256;                                          \
            int row = lin >> 4, chk = lin & 15;                               \
            uint32_t d = sB + row * 256 + (((chk ^ (row & 7))) << 4);         \
            CP_ASYNC16(d, Bhi + (size_t)(k0 + row) * LDB + bn + chk * 8);     \
            CP_ASYNC16(d + B_TILE_B, Blo + (size_t)(k0 + row) * LDB + bn + chk * 8); \
        }                                                                     \
    }                                                                         \
    CP_COMMIT();                                                              \
} while (0)

    G_LOAD(0, 0);
    G_LOAD(1, 1);

    int stg = 0;
    for (int ch = 0; ch < NCHUNK; ++ch) {
        CP_WAIT1();
        __syncthreads();
        G_LOAD(ch + 2, (stg + 2 >= 3) ? (stg - 1) : (stg + 2));

        const uint32_t abase = sb + (uint32_t)stg * STAGE_B;
        const uint32_t bbase = abase + 2 * A_TILE_B;
#pragma unroll
        for (int kk = 0; kk < 4; ++kk) {
            uint32_t ah[2][4], al[2][4];
#pragma unroll
            for (int m = 0; m < 2; ++m) {
                uint32_t r = wm + m * 16 + (lane & 15);
                uint32_t chunk = kk * 2 + (lane >> 4);
                uint32_t ad = abase + r * 128 + ((chunk ^ (r & 7)) << 4);
                ldsm_x4(ah[m], ad);
                ldsm_x4(al[m], ad + A_TILE_B);
            }
            uint32_t bh[4][4], bl[4][4];
#pragma unroll
            for (int j = 0; j < 4; ++j) {
                uint32_t krow = kk * 16 + (lane & 15);
                uint32_t chk = (uint32_t)(wn >> 3) + j * 2 + (lane >> 4);
                uint32_t bd = bbase + krow * 256 + ((chk ^ (krow & 7)) << 4);
                ldsm_x4_t(bh[j], bd);
                ldsm_x4_t(bl[j], bd + B_TILE_B);
            }
#pragma unroll
            for (int m = 0; m < 2; ++m)
#pragma unroll
                for (int j = 0; j < 4; ++j)
#pragma unroll
                    for (int h = 0; h < 2; ++h) {
                        const int n8 = j * 2 + h;
                        mma_bf16(acc[m][n8], ah[m], &bh[j][2 * h]);
                        mma_bf16(acc[m][n8], ah[m], &bl[j][2 * h]);
                        mma_bf16(acc[m][n8], al[m], &bh[j][2 * h]);
                    }
        }
        stg = (stg + 1 == 3) ? 0 : stg + 1;
    }

#pragma unroll
    for (int m = 0; m < 2; ++m) {
        const int row = bm + wm + m * 16 + (lane >> 2);
#pragma unroll
        for (int n8 = 0; n8 < 8; ++n8) {
            const int col = bn + wn + n8 * 8 + (lane & 3) * 2;
            float2 v0 = make_float2(acc[m][n8][0], acc[m][n8][1]);
            float2 v1 = make_float2(acc[m][n8][2], acc[m][n8][3]);
            if (RELU) {
                v0.x = fmaxf(v0.x, 0.f); v0.y = fmaxf(v0.y, 0.f);
                v1.x = fmaxf(v1.x, 0.f); v1.y = fmaxf(v1.y, 0.f);
            }
            *reinterpret_cast<float2*>(C + (size_t)row * LDC + col) = v0;
            *reinterpret_cast<float2*>(C + (size_t)(row + 8) * LDC + col) = v1;
        }
    }
#undef G_LOAD
}

// ================= classifier + softmax =================
__global__ void cls_softmax_kernel(const float* __restrict__ h2,
                                   const float* __restrict__ wc,
                                   float* __restrict__ out) {
    __shared__ float sh[D_DIM];
    __shared__ float red[C_DIM];
    const int b = blockIdx.x;
    const int c = threadIdx.x;
    for (int i = c; i < D_DIM; i += C_DIM) sh[i] = h2[(size_t)b * D_DIM + i];
    __syncthreads();
    float acc = 0.f;
#pragma unroll 8
    for (int k = 0; k < D_DIM; ++k)
        acc = fmaf(sh[k], wc[(size_t)k * C_DIM + c], acc);
    red[c] = acc;
    __syncthreads();
    for (int s = C_DIM / 2; s > 0; s >>= 1) {
        if (c < s) red[c] = fmaxf(red[c], red[c + s]);
        __syncthreads();
    }
    float mx = red[0];
    __syncthreads();
    float e = expf(acc - mx);
    red[c] = e;
    __syncthreads();
    for (int s = C_DIM / 2; s > 0; s >>= 1) {
        if (c < s) red[c] += red[c + s];
        __syncthreads();
    }
    out[(size_t)b * C_DIM + c] = e / red[0];
}

// ================= launch =================
extern "C" void kernel_launch(void* const* d_in, const int* in_sizes, int n_in,
                              void* d_out, int out_size) {
    const float* features  = (const float*)d_in[0];
    const int*   src_nodes = (const int*)d_in[1];
    const int*   dst_idx1  = (const int*)d_in[2];
    const int*   src_idx1  = (const int*)d_in[3];
    const float* dif_mat1  = (const float*)d_in[4];
    const int*   dst_idx2  = (const int*)d_in[5];
    const int*   src_idx2  = (const int*)d_in[6];
    const float* dif_mat2  = (const float*)d_in[7];
    const float* w1        = (const float*)d_in[8];
    const float* w2        = (const float*)d_in[9];
    const float* w_cls     = (const float*)d_in[10];
    float* out = (float*)d_out;

    float *cat1, *h1, *cat2, *h2;
    int* gidx1;
    uint8_t *a8, *xt8;
    __half *a2, *h1f16;
    __nv_bfloat16 *c1hi, *c1lo, *w1hi, *w1lo, *c2hi, *c2lo, *w2hi, *w2lo;
    cudaGetSymbolAddress((void**)&cat1,  g_cat1);
    cudaGetSymbolAddress((void**)&h1,    g_h1);
    cudaGetSymbolAddress((void**)&cat2,  g_cat2);
    cudaGetSymbolAddress((void**)&h2,    g_h2);
    cudaGetSymbolAddress((void**)&gidx1, g_gidx1);
    cudaGetSymbolAddress((void**)&a8,    g_a8);
    cudaGetSymbolAddress((void**)&xt8,   g_xt8);
    cudaGetSymbolAddress((void**)&a2,    g_a2);
    cudaGetSymbolAddress((void**)&h1f16, g_h1f16);
    cudaGetSymbolAddress((void**)&c1hi,  g_c1hi);
    cudaGetSymbolAddress((void**)&c1lo,  g_c1lo);
    cudaGetSymbolAddress((void**)&w1hi,  g_w1hi);
    cudaGetSymbolAddress((void**)&w1lo,  g_w1lo);
    cudaGetSymbolAddress((void**)&c2hi,  g_c2hi);
    cudaGetSymbolAddress((void**)&c2lo,  g_c2lo);
    cudaGetSymbolAddress((void**)&w2hi,  g_w2hi);
    cudaGetSymbolAddress((void**)&w2lo,  g_w2lo);

    cudaFuncSetAttribute((const void*)gemm1_fp8,
                         cudaFuncAttributeMaxDynamicSharedMemorySize, P_SMEM);
    cudaFuncSetAttribute((const void*)gemm2_f16,
                         cudaFuncAttributeMaxDynamicSharedMemorySize, Q_SMEM);
    cudaFuncSetAttribute((const void*)gemm_hmma3<1024, 1024, D_DIM, D_DIM, true>,
                         cudaFuncAttributeMaxDynamicSharedMemorySize, GSMEM);

    // 0) index composition, dst gather, operand prep
    build_gidx_kernel<<<(S1_CNT + 255) / 256, 256>>>(src_nodes, src_idx1, gidx1, S1_CNT);
    gather_cat_kernel<<<B1_CNT, 128>>>(features, dst_idx1, src_nodes, cat1);
    prep_xt8_kernel<<<dim3(S1_CNT / 128, F_DIM / 64), 128>>>(features, gidx1, xt8);
    {
        int n8 = (B1_CNT * S1_CNT) / 8;
        scale_a8_kernel<<<n8 / 256, 256>>>(dif_mat1, a8, n8);
    }

    // 1) agg1 = dif_mat1 @ X -> cat1[:, 0:512]   (fp8 e4m3)
    gemm1_fp8<<<dim3(F_DIM / 128, B1_CNT / 128), 256, P_SMEM>>>(a8, xt8, cat1);

    // 2) split cat1 / w1 (bf16), h1 = relu(cat1 @ w1)  (bf16 3-term)
    {
        int n8 = (B1_CNT * 1024) / 8;
        split_kernel<<<n8 / 256, 256>>>(cat1, c1hi, c1lo, n8);
        int m8 = (1024 * D_DIM) / 8;
        split_kernel<<<m8 / 256, 256>>>(w1, w1hi, w1lo, m8);
    }
    gemm_hmma3<1024, 1024, D_DIM, D_DIM, true>
        <<<dim3(D_DIM / 128, B1_CNT / 128), 256, GSMEM>>>(c1hi, c1lo, w1hi, w1lo, h1);

    // 3) layer 2: agg2 on fp16 HMMA (gathered), h2 on bf16 3-term
    {
        int n4 = (B1_CNT * D_DIM) / 4;
        f32_to_f16_kernel<<<n4 / 256, 256>>>(h1, h1f16, n4);
        int a8n = (B2_CNT * S2_CNT) / 8;
        scale_f16_kernel<<<(a8n + 255) / 256, 256>>>(dif_mat2, a2, a8n);
    }
    gather_cat_kernel<<<B2_CNT, 128>>>(h1, dst_idx2, nullptr, cat2);
    gemm2_f16<<<dim3(D_DIM / 128, B2_CNT / 128), 256, Q_SMEM>>>(a2, h1f16, src_idx2, cat2);
    {
        int n8 = (B2_CNT * 1024) / 8;
        split_kernel<<<(n8 + 255) / 256, 256>>>(cat2, c2hi, c2lo, n8);
        int m8 = (1024 * D_DIM) / 8;
        split_kernel<<<m8 / 256, 256>>>(w2, w2hi, w2lo, m8);
    }
    gemm_hmma3<1024, 1024, D_DIM, D_DIM, true>
        <<<dim3(D_DIM / 128, B2_CNT / 128), 256, GSMEM>>>(c2hi, c2lo, w2hi, w2lo, h2);

    // 4) out = softmax(h2 @ w_cls)
    cls_softmax_kernel<<<B2_CNT, C_DIM>>>(h2, w_cls, out);
}